// round 9
// baseline (speedup 1.0000x reference)
#include <cuda_runtime.h>
#include <cuda_bf16.h>
#include <cstdint>

#define N_NODES 40000
#define N_EDGES 640000
#define D 128

// ---------------- scratch (device globals: no allocations allowed) ----------
static __device__ float g_Y  [N_NODES * D];   // per-node message output
static __device__ float g_AGG[N_NODES * D];   // scatter-mean result
static __device__ int   g_ROW[N_NODES + 1];   // CSR row offsets (by dst)
static __device__ int   g_CUR[N_NODES];       // counts, then fill cursors
static __device__ int   g_EIDX[N_EDGES];      // src ids grouped by dst
static __device__ int   g_is64;               // edge_index dtype flag
// pre-split weights (bf16 hi / lo), [n][k] row-major:
//   Wm1 @ 0 (16384), Wm2 @ 16384, Wu1 @ 32768 (32768), Wu2 @ 65536
static __device__ unsigned short g_Wh[81920];
static __device__ unsigned short g_Wl[81920];

// ---------------- helpers ----------------------------------------------------
__device__ __forceinline__ uint32_t smem_u32(const void* p) {
    return (uint32_t)__cvta_generic_to_shared(p);
}

// split 4 fp32 -> bf16 hi (truncate) pairs + bf16 lo (rn of residual) pairs
__device__ __forceinline__ void split4(float4 v, uint32_t& h01, uint32_t& h23,
                                       uint32_t& l01, uint32_t& l23) {
    uint32_t u0 = __float_as_uint(v.x), u1 = __float_as_uint(v.y);
    uint32_t u2 = __float_as_uint(v.z), u3 = __float_as_uint(v.w);
    asm("prmt.b32 %0, %1, %2, 0x7632;" : "=r"(h01) : "r"(u0), "r"(u1));
    asm("prmt.b32 %0, %1, %2, 0x7632;" : "=r"(h23) : "r"(u2), "r"(u3));
    float lo0 = v.x - __uint_as_float(u0 & 0xFFFF0000u);
    float lo1 = v.y - __uint_as_float(u1 & 0xFFFF0000u);
    float lo2 = v.z - __uint_as_float(u2 & 0xFFFF0000u);
    float lo3 = v.w - __uint_as_float(u3 & 0xFFFF0000u);
    asm("cvt.rn.bf16x2.f32 %0, %1, %2;" : "=r"(l01) : "f"(lo1), "f"(lo0));
    asm("cvt.rn.bf16x2.f32 %0, %1, %2;" : "=r"(l23) : "f"(lo3), "f"(lo2));
}

#define LDSM_X4(r0, r1, r2, r3, addr) \
    asm volatile("ldmatrix.sync.aligned.m8n8.x4.shared.b16 {%0,%1,%2,%3}, [%4];" \
        : "=r"(r0), "=r"(r1), "=r"(r2), "=r"(r3) : "r"(addr))

#define MMA_BF16(c, a, b) \
    asm volatile("mma.sync.aligned.m16n8k16.row.col.f32.bf16.bf16.f32 " \
        "{%0,%1,%2,%3}, {%4,%5,%6,%7}, {%8,%9}, {%0,%1,%2,%3};" \
        : "+f"((c)[0]), "+f"((c)[1]), "+f"((c)[2]), "+f"((c)[3]) \
        : "r"((a)[0]), "r"((a)[1]), "r"((a)[2]), "r"((a)[3]), \
          "r"((b)[0]), "r"((b)[1]))

// ---- shared GEMM building blocks (tile M=64 x N=128, K-chunk 128) ----------
// A tile fill: 64x128 fp32 -> bf16 hi/lo split into sA (stride 136 shorts)
__device__ __forceinline__ void load_A_split(const float* __restrict__ Asrc,
                                             unsigned short* sAhi, unsigned short* sAlo,
                                             int tid) {
    #pragma unroll
    for (int it = 0; it < 8; ++it) {
        int idx  = tid + it * 256;
        int row  = idx >> 5;
        int col4 = idx & 31;
        float4 v = *reinterpret_cast<const float4*>(Asrc + (size_t)row * D + col4 * 4);
        uint32_t h01, h23, l01, l23;
        split4(v, h01, h23, l01, l23);
        *reinterpret_cast<uint2*>(sAhi + row * 136 + col4 * 4) = make_uint2(h01, h23);
        *reinterpret_cast<uint2*>(sAlo + row * 136 + col4 * 4) = make_uint2(l01, l23);
    }
}
// B tile fill: copy pre-split bf16 weights [128 rows x 128 k]
__device__ __forceinline__ void load_B(int woff, int kstride, int kc,
                                       unsigned short* sBhi, unsigned short* sBlo,
                                       int tid) {
    #pragma unroll
    for (int it = 0; it < 8; ++it) {
        int idx = tid + it * 256;
        int row = idx >> 4;
        int c8  = idx & 15;
        size_t gsrc = (size_t)woff + (size_t)row * kstride + kc * 128 + c8 * 8;
        *reinterpret_cast<uint4*>(sBhi + row * 136 + c8 * 8) =
            *reinterpret_cast<const uint4*>(g_Wh + gsrc);
        *reinterpret_cast<uint4*>(sBlo + row * 136 + c8 * 8) =
            *reinterpret_cast<const uint4*>(g_Wl + gsrc);
    }
}
// 3-pass mma over one 128-K chunk, accumulate into c
__device__ __forceinline__ void mma_chunk(const unsigned short* sAhi, const unsigned short* sAlo,
                                          const unsigned short* sBhi, const unsigned short* sBlo,
                                          float c[2][4][4], int lane, int wm, int wn) {
    const int a_row = lane & 15, a_kh = (lane >> 4) * 8;
    const int b_row = (lane >> 4) * 8 + (lane & 7);
    const int b_kh  = ((lane >> 3) & 1) * 8;
    #pragma unroll
    for (int ks = 0; ks < 8; ++ks) {
        const int kb = ks * 16;
        uint32_t ah[2][4], al[2][4], bh[4][2], bl[4][2];
        #pragma unroll
        for (int mt = 0; mt < 2; ++mt) {
            uint32_t addr = smem_u32(sAhi + (wm + mt * 16 + a_row) * 136 + kb + a_kh);
            LDSM_X4(ah[mt][0], ah[mt][1], ah[mt][2], ah[mt][3], addr);
            addr = smem_u32(sAlo + (wm + mt * 16 + a_row) * 136 + kb + a_kh);
            LDSM_X4(al[mt][0], al[mt][1], al[mt][2], al[mt][3], addr);
        }
        #pragma unroll
        for (int bt = 0; bt < 2; ++bt) {
            uint32_t addr = smem_u32(sBhi + (wn + bt * 16 + b_row) * 136 + kb + b_kh);
            LDSM_X4(bh[bt*2][0], bh[bt*2][1], bh[bt*2+1][0], bh[bt*2+1][1], addr);
            addr = smem_u32(sBlo + (wn + bt * 16 + b_row) * 136 + kb + b_kh);
            LDSM_X4(bl[bt*2][0], bl[bt*2][1], bl[bt*2+1][0], bl[bt*2+1][1], addr);
        }
        #pragma unroll
        for (int mt = 0; mt < 2; ++mt)
            #pragma unroll
            for (int nt = 0; nt < 4; ++nt) {
                MMA_BF16(c[mt][nt], ah[mt], bh[nt]);
                MMA_BF16(c[mt][nt], ah[mt], bl[nt]);
                MMA_BF16(c[mt][nt], al[mt], bh[nt]);
            }
    }
}
__device__ __forceinline__ void zero_c(float c[2][4][4]) {
    #pragma unroll
    for (int i = 0; i < 2; i++)
        #pragma unroll
        for (int j = 0; j < 4; j++)
            #pragma unroll
            for (int q = 0; q < 4; q++) c[i][j][q] = 0.0f;
}
// bias(+relu) the accumulators, split to bf16 hi/lo, write as next A tile
__device__ __forceinline__ void epi_split_to_sA(float c[2][4][4], const float* sb,
                                                unsigned short* sAhi, unsigned short* sAlo,
                                                int lane, int wm, int wn) {
    const int g = lane >> 2, cl = (lane & 3) * 2;
    #pragma unroll
    for (int mt = 0; mt < 2; ++mt) {
        const int row0 = wm + mt * 16 + g;
        #pragma unroll
        for (int nt = 0; nt < 4; ++nt) {
            const int col = wn + nt * 8 + cl;
            float h0 = fmaxf(c[mt][nt][0] + sb[col],     0.f);
            float h1 = fmaxf(c[mt][nt][1] + sb[col + 1], 0.f);
            float h2 = fmaxf(c[mt][nt][2] + sb[col],     0.f);
            float h3 = fmaxf(c[mt][nt][3] + sb[col + 1], 0.f);
            uint32_t u0 = __float_as_uint(h0), u1 = __float_as_uint(h1);
            uint32_t u2 = __float_as_uint(h2), u3 = __float_as_uint(h3);
            uint32_t hi01, hi23, lo01, lo23;
            asm("prmt.b32 %0, %1, %2, 0x7632;" : "=r"(hi01) : "r"(u0), "r"(u1));
            asm("prmt.b32 %0, %1, %2, 0x7632;" : "=r"(hi23) : "r"(u2), "r"(u3));
            float r0 = h0 - __uint_as_float(u0 & 0xFFFF0000u);
            float r1 = h1 - __uint_as_float(u1 & 0xFFFF0000u);
            float r2 = h2 - __uint_as_float(u2 & 0xFFFF0000u);
            float r3 = h3 - __uint_as_float(u3 & 0xFFFF0000u);
            asm("cvt.rn.bf16x2.f32 %0, %1, %2;" : "=r"(lo01) : "f"(r1), "f"(r0));
            asm("cvt.rn.bf16x2.f32 %0, %1, %2;" : "=r"(lo23) : "f"(r3), "f"(r2));
            *reinterpret_cast<uint32_t*>(sAhi + row0 * 136 + col)       = hi01;
            *reinterpret_cast<uint32_t*>(sAlo + row0 * 136 + col)       = lo01;
            *reinterpret_cast<uint32_t*>(sAhi + (row0 + 8) * 136 + col) = hi23;
            *reinterpret_cast<uint32_t*>(sAlo + (row0 + 8) * 136 + col) = lo23;
        }
    }
}

// ---------------- fused message MLP: Y = mlp_m(x), per 64-row tile ----------
__global__ __launch_bounds__(256, 2)
void msg_kernel(const float* __restrict__ x, const float* __restrict__ bm1,
                const float* __restrict__ bm2, float* __restrict__ Y)
{
    extern __shared__ char smc[];
    float* sb1 = (float*)smc;            // 512
    float* sb2 = sb1 + 128;              // 512
    unsigned short* sAhi = (unsigned short*)(smc + 1024);
    unsigned short* sAlo = sAhi + 64 * 136;
    unsigned short* sBhi = sAlo + 64 * 136;
    unsigned short* sBlo = sBhi + 128 * 136;

    const int tid = threadIdx.x, lane = tid & 31, wid = tid >> 5;
    const int wm = (wid >> 2) * 32, wn = (wid & 3) * 32;
    const int m0 = blockIdx.x * 64;

    if (tid < 128) { sb1[tid] = bm1[tid]; sb2[tid] = bm2[tid]; }
    load_A_split(x + (size_t)m0 * D, sAhi, sAlo, tid);
    load_B(0, 128, 0, sBhi, sBlo, tid);
    __syncthreads();

    float c[2][4][4];
    zero_c(c);
    mma_chunk(sAhi, sAlo, sBhi, sBlo, c, lane, wm, wn);
    __syncthreads();                                  // everyone done reading tiles

    epi_split_to_sA(c, sb1, sAhi, sAlo, lane, wm, wn);  // H1 -> A tile (relu)
    load_B(16384, 128, 0, sBhi, sBlo, tid);             // Wm2
    __syncthreads();

    zero_c(c);
    mma_chunk(sAhi, sAlo, sBhi, sBlo, c, lane, wm, wn);

    const int g = lane >> 2, cl = (lane & 3) * 2;
    #pragma unroll
    for (int mt = 0; mt < 2; ++mt) {
        const int m = m0 + wm + mt * 16 + g;
        #pragma unroll
        for (int nt = 0; nt < 4; ++nt) {
            const int n = wn + nt * 8 + cl;
            float2 o0 = make_float2(c[mt][nt][0] + sb2[n], c[mt][nt][1] + sb2[n + 1]);
            float2 o1 = make_float2(c[mt][nt][2] + sb2[n], c[mt][nt][3] + sb2[n + 1]);
            *reinterpret_cast<float2*>(Y + (size_t)m * D + n)       = o0;
            *reinterpret_cast<float2*>(Y + (size_t)(m + 8) * D + n) = o1;
        }
    }
}

// ---------------- fused update MLP + residual + LayerNorm -------------------
__global__ __launch_bounds__(256, 2)
void upd_kernel(const float* __restrict__ x, const float* __restrict__ AGG,
                const float* __restrict__ bu1, const float* __restrict__ bu2,
                const float* __restrict__ gamma, const float* __restrict__ beta,
                float* __restrict__ out)
{
    extern __shared__ char smc[];
    float* sb1  = (float*)smc;           // 512
    float* sb2  = sb1 + 128;
    float* sg   = sb2 + 128;
    float* sbt  = sg + 128;
    float* ssum = sbt + 128;             // 64 floats
    float* ssq  = ssum + 64;             // 64 floats
    unsigned short* sAhi = (unsigned short*)(smc + 2560);
    unsigned short* sAlo = sAhi + 64 * 136;
    unsigned short* sBhi = sAlo + 64 * 136;
    unsigned short* sBlo = sBhi + 128 * 136;

    const int tid = threadIdx.x, lane = tid & 31, wid = tid >> 5;
    const int wm = (wid >> 2) * 32, wn = (wid & 3) * 32;
    const int m0 = blockIdx.x * 64;

    if (tid < 128) {
        sb1[tid] = bu1[tid]; sb2[tid] = bu2[tid];
        sg[tid] = gamma[tid]; sbt[tid] = beta[tid];
        if (tid < 64) { ssum[tid] = 0.f; ssq[tid] = 0.f; }
    }

    float c[2][4][4];
    zero_c(c);

    // K chunk 0: x part of concat
    load_A_split(x + (size_t)m0 * D, sAhi, sAlo, tid);
    load_B(32768, 256, 0, sBhi, sBlo, tid);
    __syncthreads();
    mma_chunk(sAhi, sAlo, sBhi, sBlo, c, lane, wm, wn);
    __syncthreads();
    // K chunk 1: AGG part of concat
    load_A_split(AGG + (size_t)m0 * D, sAhi, sAlo, tid);
    load_B(32768, 256, 1, sBhi, sBlo, tid);
    __syncthreads();
    mma_chunk(sAhi, sAlo, sBhi, sBlo, c, lane, wm, wn);
    __syncthreads();

    epi_split_to_sA(c, sb1, sAhi, sAlo, lane, wm, wn);  // U1 -> A tile (relu)
    load_B(65536, 128, 0, sBhi, sBlo, tid);             // Wu2
    __syncthreads();

    zero_c(c);
    mma_chunk(sAhi, sAlo, sBhi, sBlo, c, lane, wm, wn);
    __syncthreads();

    // h = c + bias + residual(x); keep in c. Row partial sums -> smem.
    const int g = lane >> 2, cl = (lane & 3) * 2;
    #pragma unroll
    for (int mt = 0; mt < 2; ++mt) {
        const int row0 = wm + mt * 16 + g;
        float s0 = 0.f, q0 = 0.f, s1 = 0.f, q1 = 0.f;
        #pragma unroll
        for (int nt = 0; nt < 4; ++nt) {
            const int col = wn + nt * 8 + cl;
            float2 r0 = *reinterpret_cast<const float2*>(x + (size_t)(m0 + row0) * D + col);
            float2 r1 = *reinterpret_cast<const float2*>(x + (size_t)(m0 + row0 + 8) * D + col);
            float h0 = c[mt][nt][0] + sb2[col]     + r0.x;
            float h1 = c[mt][nt][1] + sb2[col + 1] + r0.y;
            float h2 = c[mt][nt][2] + sb2[col]     + r1.x;
            float h3 = c[mt][nt][3] + sb2[col + 1] + r1.y;
            c[mt][nt][0] = h0; c[mt][nt][1] = h1; c[mt][nt][2] = h2; c[mt][nt][3] = h3;
            s0 += h0 + h1; q0 += h0 * h0 + h1 * h1;
            s1 += h2 + h3; q1 += h2 * h2 + h3 * h3;
        }
        // reduce over the 4 lanes sharing this row (cl groups)
        #pragma unroll
        for (int o = 1; o <= 2; o <<= 1) {
            s0 += __shfl_xor_sync(0xffffffffu, s0, o);
            q0 += __shfl_xor_sync(0xffffffffu, q0, o);
            s1 += __shfl_xor_sync(0xffffffffu, s1, o);
            q1 += __shfl_xor_sync(0xffffffffu, q1, o);
        }
        if ((lane & 3) == 0) {
            atomicAdd(&ssum[row0], s0);     atomicAdd(&ssq[row0], q0);
            atomicAdd(&ssum[row0 + 8], s1); atomicAdd(&ssq[row0 + 8], q1);
        }
    }
    __syncthreads();

    #pragma unroll
    for (int mt = 0; mt < 2; ++mt) {
        const int row0 = wm + mt * 16 + g;
        float mu0 = ssum[row0] * (1.f / 128.f);
        float v0  = ssq[row0] * (1.f / 128.f) - mu0 * mu0;
        float rs0 = rsqrtf(v0 + 1e-5f);
        float mu1 = ssum[row0 + 8] * (1.f / 128.f);
        float v1  = ssq[row0 + 8] * (1.f / 128.f) - mu1 * mu1;
        float rs1 = rsqrtf(v1 + 1e-5f);
        #pragma unroll
        for (int nt = 0; nt < 4; ++nt) {
            const int col = wn + nt * 8 + cl;
            float2 o0, o1;
            o0.x = (c[mt][nt][0] - mu0) * rs0 * sg[col]     + sbt[col];
            o0.y = (c[mt][nt][1] - mu0) * rs0 * sg[col + 1] + sbt[col + 1];
            o1.x = (c[mt][nt][2] - mu1) * rs1 * sg[col]     + sbt[col];
            o1.y = (c[mt][nt][3] - mu1) * rs1 * sg[col + 1] + sbt[col + 1];
            *reinterpret_cast<float2*>(out + (size_t)(m0 + row0) * D + col)     = o0;
            *reinterpret_cast<float2*>(out + (size_t)(m0 + row0 + 8) * D + col) = o1;
        }
    }
}

// ---------------- weight pre-split -------------------------------------------
__global__ void wsplit_kernel(const float* __restrict__ Wm1, const float* __restrict__ Wm2,
                              const float* __restrict__ Wu1, const float* __restrict__ Wu2)
{
    int i = blockIdx.x * blockDim.x + threadIdx.x;
    if (i >= 81920) return;
    float f;
    if      (i < 16384) f = Wm1[i];
    else if (i < 32768) f = Wm2[i - 16384];
    else if (i < 65536) f = Wu1[i - 32768];
    else                f = Wu2[i - 65536];
    uint32_t u = __float_as_uint(f);
    g_Wh[i] = (unsigned short)(u >> 16);
    float lo = f - __uint_as_float(u & 0xFFFF0000u);
    g_Wl[i] = __bfloat16_as_ushort(__float2bfloat16(lo));
}

// ---------------- edge dtype sniff -------------------------------------------
__global__ void detect_kernel(const int* __restrict__ e) {
    if (threadIdx.x == 0) {
        int any = 0;
        for (int i = 1; i < 256; i += 2) any |= e[i];
        g_is64 = (any == 0) ? 1 : 0;
    }
}

// ---------------- CSR build (scatter-mean without float atomics) ------------
__global__ void zero_cur_kernel(int* __restrict__ CUR) {
    int i = blockIdx.x * blockDim.x + threadIdx.x;
    if (i < N_NODES) CUR[i] = 0;
}
__global__ void count_kernel(const void* __restrict__ eidx, int* __restrict__ CUR) {
    int e = blockIdx.x * blockDim.x + threadIdx.x;     // 2500*256 = E exact
    int dst = g_is64 ? (int)reinterpret_cast<const long long*>(eidx)[N_EDGES + e]
                     : reinterpret_cast<const int*>(eidx)[N_EDGES + e];
    atomicAdd(&CUR[dst], 1);
}
__global__ void scan_kernel(int* __restrict__ CUR, int* __restrict__ ROW) {
    __shared__ int bs[1024];
    const int t = threadIdx.x;
    const int base = t * 40;
    int s = 0;
    for (int i = 0; i < 40; i++) {
        int idx = base + i;
        if (idx < N_NODES) s += CUR[idx];
    }
    bs[t] = s;
    __syncthreads();
    for (int off = 1; off < 1024; off <<= 1) {
        int v = (t >= off) ? bs[t - off] : 0;
        __syncthreads();
        bs[t] += v;
        __syncthreads();
    }
    int run = (t == 0) ? 0 : bs[t - 1];
    for (int i = 0; i < 40; i++) {
        int idx = base + i;
        if (idx < N_NODES) {
            int cv = CUR[idx];
            ROW[idx] = run;
            CUR[idx] = run;       // cursor for fill
            run += cv;
        }
    }
    if (t == 0) ROW[N_NODES] = N_EDGES;
}
__global__ void fill_kernel(const void* __restrict__ eidx, int* __restrict__ CUR,
                            int* __restrict__ EIDX) {
    int e = blockIdx.x * blockDim.x + threadIdx.x;
    int src, dst;
    if (g_is64) {
        const long long* p = reinterpret_cast<const long long*>(eidx);
        src = (int)p[e]; dst = (int)p[N_EDGES + e];
    } else {
        const int* p = reinterpret_cast<const int*>(eidx);
        src = p[e]; dst = p[N_EDGES + e];
    }
    int pos = atomicAdd(&CUR[dst], 1);
    EIDX[pos] = src;
}
// one warp per node: sum Y[src] over incoming edges, divide by degree
__global__ void gather_kernel(const float* __restrict__ Y, const int* __restrict__ ROW,
                              const int* __restrict__ EIDX, float* __restrict__ AGG) {
    const int n    = blockIdx.x * 8 + (threadIdx.x >> 5);
    const int lane = threadIdx.x & 31;
    const int s = ROW[n], e = ROW[n + 1];
    float4 acc = make_float4(0.f, 0.f, 0.f, 0.f);
    for (int base = s; base < e; base += 32) {
        const int cnt = min(32, e - base);
        int idx = (base + lane < e) ? EIDX[base + lane] : 0;
        for (int j = 0; j < cnt; j++) {
            int src = __shfl_sync(0xffffffffu, idx, j);
            float4 v = reinterpret_cast<const float4*>(Y + (size_t)src * D)[lane];
            acc.x += v.x; acc.y += v.y; acc.z += v.z; acc.w += v.w;
        }
    }
    const float sc = 1.0f / (float)max(e - s, 1);
    acc.x *= sc; acc.y *= sc; acc.z *= sc; acc.w *= sc;
    reinterpret_cast<float4*>(AGG + (size_t)n * D)[lane] = acc;
}

// ---------------- launch -----------------------------------------------------
extern "C" void kernel_launch(void* const* d_in, const int* in_sizes, int n_in,
                              void* d_out, int out_size)
{
    const float* x     = (const float*)d_in[0];
    const void*  eidx  =               d_in[1];
    const float* Wm1   = (const float*)d_in[2];
    const float* bm1   = (const float*)d_in[3];
    const float* Wm2   = (const float*)d_in[4];
    const float* bm2   = (const float*)d_in[5];
    const float* Wu1   = (const float*)d_in[6];
    const float* bu1   = (const float*)d_in[7];
    const float* Wu2   = (const float*)d_in[8];
    const float* bu2   = (const float*)d_in[9];
    const float* gamma = (const float*)d_in[10];
    const float* beta  = (const float*)d_in[11];
    float* out = (float*)d_out;

    void *pY, *pAGG, *pROW, *pCUR, *pEIDX;
    cudaGetSymbolAddress(&pY,    g_Y);
    cudaGetSymbolAddress(&pAGG,  g_AGG);
    cudaGetSymbolAddress(&pROW,  g_ROW);
    cudaGetSymbolAddress(&pCUR,  g_CUR);
    cudaGetSymbolAddress(&pEIDX, g_EIDX);

    // smem: hdr + A hi/lo (64x136) + B hi/lo (128x136), shorts
    const int SM1 = 1024 + 2 * (64 * 136 * 2) + 2 * (128 * 136 * 2);  // 105472
    const int SM2 = 2560 + 2 * (64 * 136 * 2) + 2 * (128 * 136 * 2);  // 107008
    cudaFuncSetAttribute(msg_kernel, cudaFuncAttributeMaxDynamicSharedMemorySize, SM1);
    cudaFuncSetAttribute(upd_kernel, cudaFuncAttributeMaxDynamicSharedMemorySize, SM2);

    detect_kernel  <<<1, 32>>>((const int*)eidx);
    wsplit_kernel  <<<320, 256>>>(Wm1, Wm2, Wu1, Wu2);
    zero_cur_kernel<<<157, 256>>>((int*)pCUR);
    count_kernel   <<<2500, 256>>>(eidx, (int*)pCUR);
    scan_kernel    <<<1, 1024>>>((int*)pCUR, (int*)pROW);
    fill_kernel    <<<2500, 256>>>(eidx, (int*)pCUR, (int*)pEIDX);

    // fused message MLP (per-node, algebraically identical to per-edge)
    msg_kernel<<<625, 256, SM1>>>(x, bm1, bm2, (float*)pY);
    // CSR gather-mean
    gather_kernel<<<5000, 256>>>((const float*)pY, (const int*)pROW,
                                 (const int*)pEIDX, (float*)pAGG);
    // fused update MLP + residual + LayerNorm
    upd_kernel<<<625, 256, SM2>>>(x, (const float*)pAGG, bu1, bu2, gamma, beta, out);
}

// round 10
// speedup vs baseline: 1.0433x; 1.0433x over previous
#include <cuda_runtime.h>
#include <cuda_bf16.h>
#include <cuda_fp16.h>
#include <cstdint>

#define N_NODES 40000
#define N_EDGES 640000
#define D 128

// ---------------- scratch (device globals: no allocations allowed) ----------
static __device__ __half g_Y [N_NODES * D];   // per-node message output (fp16)
static __device__ float g_AGG[N_NODES * D];   // scatter-mean result
static __device__ int   g_ROW[N_NODES + 1];   // CSR row offsets (by dst)
static __device__ int   g_CUR[N_NODES];       // counts, then fill cursors
static __device__ int   g_EIDX[N_EDGES];      // src ids grouped by dst
static __device__ int   g_is64;               // edge_index dtype flag
// pre-split weights (bf16 hi / lo), [n][k] row-major:
//   Wm1 @ 0 (16384), Wm2 @ 16384, Wu1 @ 32768 (32768), Wu2 @ 65536
static __device__ unsigned short g_Wh[81920];
static __device__ unsigned short g_Wl[81920];

// ---------------- helpers ----------------------------------------------------
__device__ __forceinline__ uint32_t smem_u32(const void* p) {
    return (uint32_t)__cvta_generic_to_shared(p);
}

// split 4 fp32 -> bf16 hi (truncate) pairs + bf16 lo (rn of residual) pairs
__device__ __forceinline__ void split4(float4 v, uint32_t& h01, uint32_t& h23,
                                       uint32_t& l01, uint32_t& l23) {
    uint32_t u0 = __float_as_uint(v.x), u1 = __float_as_uint(v.y);
    uint32_t u2 = __float_as_uint(v.z), u3 = __float_as_uint(v.w);
    asm("prmt.b32 %0, %1, %2, 0x7632;" : "=r"(h01) : "r"(u0), "r"(u1));
    asm("prmt.b32 %0, %1, %2, 0x7632;" : "=r"(h23) : "r"(u2), "r"(u3));
    float lo0 = v.x - __uint_as_float(u0 & 0xFFFF0000u);
    float lo1 = v.y - __uint_as_float(u1 & 0xFFFF0000u);
    float lo2 = v.z - __uint_as_float(u2 & 0xFFFF0000u);
    float lo3 = v.w - __uint_as_float(u3 & 0xFFFF0000u);
    asm("cvt.rn.bf16x2.f32 %0, %1, %2;" : "=r"(l01) : "f"(lo1), "f"(lo0));
    asm("cvt.rn.bf16x2.f32 %0, %1, %2;" : "=r"(l23) : "f"(lo3), "f"(lo2));
}

#define LDSM_X4(r0, r1, r2, r3, addr) \
    asm volatile("ldmatrix.sync.aligned.m8n8.x4.shared.b16 {%0,%1,%2,%3}, [%4];" \
        : "=r"(r0), "=r"(r1), "=r"(r2), "=r"(r3) : "r"(addr))

#define MMA_BF16(c, a, b) \
    asm volatile("mma.sync.aligned.m16n8k16.row.col.f32.bf16.bf16.f32 " \
        "{%0,%1,%2,%3}, {%4,%5,%6,%7}, {%8,%9}, {%0,%1,%2,%3};" \
        : "+f"((c)[0]), "+f"((c)[1]), "+f"((c)[2]), "+f"((c)[3]) \
        : "r"((a)[0]), "r"((a)[1]), "r"((a)[2]), "r"((a)[3]), \
          "r"((b)[0]), "r"((b)[1]))

// ---- shared GEMM building blocks (tile M=64 x N=128, K-chunk 128) ----------
__device__ __forceinline__ void load_A_split(const float* __restrict__ Asrc,
                                             unsigned short* sAhi, unsigned short* sAlo,
                                             int tid) {
    #pragma unroll
    for (int it = 0; it < 8; ++it) {
        int idx  = tid + it * 256;
        int row  = idx >> 5;
        int col4 = idx & 31;
        float4 v = *reinterpret_cast<const float4*>(Asrc + (size_t)row * D + col4 * 4);
        uint32_t h01, h23, l01, l23;
        split4(v, h01, h23, l01, l23);
        *reinterpret_cast<uint2*>(sAhi + row * 136 + col4 * 4) = make_uint2(h01, h23);
        *reinterpret_cast<uint2*>(sAlo + row * 136 + col4 * 4) = make_uint2(l01, l23);
    }
}
__device__ __forceinline__ void load_B(int woff, int kstride, int kc,
                                       unsigned short* sBhi, unsigned short* sBlo,
                                       int tid) {
    #pragma unroll
    for (int it = 0; it < 8; ++it) {
        int idx = tid + it * 256;
        int row = idx >> 4;
        int c8  = idx & 15;
        size_t gsrc = (size_t)woff + (size_t)row * kstride + kc * 128 + c8 * 8;
        *reinterpret_cast<uint4*>(sBhi + row * 136 + c8 * 8) =
            *reinterpret_cast<const uint4*>(g_Wh + gsrc);
        *reinterpret_cast<uint4*>(sBlo + row * 136 + c8 * 8) =
            *reinterpret_cast<const uint4*>(g_Wl + gsrc);
    }
}
__device__ __forceinline__ void mma_chunk(const unsigned short* sAhi, const unsigned short* sAlo,
                                          const unsigned short* sBhi, const unsigned short* sBlo,
                                          float c[2][4][4], int lane, int wm, int wn) {
    const int a_row = lane & 15, a_kh = (lane >> 4) * 8;
    const int b_row = (lane >> 4) * 8 + (lane & 7);
    const int b_kh  = ((lane >> 3) & 1) * 8;
    #pragma unroll
    for (int ks = 0; ks < 8; ++ks) {
        const int kb = ks * 16;
        uint32_t ah[2][4], al[2][4], bh[4][2], bl[4][2];
        #pragma unroll
        for (int mt = 0; mt < 2; ++mt) {
            uint32_t addr = smem_u32(sAhi + (wm + mt * 16 + a_row) * 136 + kb + a_kh);
            LDSM_X4(ah[mt][0], ah[mt][1], ah[mt][2], ah[mt][3], addr);
            addr = smem_u32(sAlo + (wm + mt * 16 + a_row) * 136 + kb + a_kh);
            LDSM_X4(al[mt][0], al[mt][1], al[mt][2], al[mt][3], addr);
        }
        #pragma unroll
        for (int bt = 0; bt < 2; ++bt) {
            uint32_t addr = smem_u32(sBhi + (wn + bt * 16 + b_row) * 136 + kb + b_kh);
            LDSM_X4(bh[bt*2][0], bh[bt*2][1], bh[bt*2+1][0], bh[bt*2+1][1], addr);
            addr = smem_u32(sBlo + (wn + bt * 16 + b_row) * 136 + kb + b_kh);
            LDSM_X4(bl[bt*2][0], bl[bt*2][1], bl[bt*2+1][0], bl[bt*2+1][1], addr);
        }
        #pragma unroll
        for (int mt = 0; mt < 2; ++mt)
            #pragma unroll
            for (int nt = 0; nt < 4; ++nt) {
                MMA_BF16(c[mt][nt], ah[mt], bh[nt]);
                MMA_BF16(c[mt][nt], ah[mt], bl[nt]);
                MMA_BF16(c[mt][nt], al[mt], bh[nt]);
            }
    }
}
__device__ __forceinline__ void zero_c(float c[2][4][4]) {
    #pragma unroll
    for (int i = 0; i < 2; i++)
        #pragma unroll
        for (int j = 0; j < 4; j++)
            #pragma unroll
            for (int q = 0; q < 4; q++) c[i][j][q] = 0.0f;
}
// bias(+relu) the accumulators, split to bf16 hi/lo, write as next A tile
__device__ __forceinline__ void epi_split_to_sA(float c[2][4][4], const float* sb,
                                                unsigned short* sAhi, unsigned short* sAlo,
                                                int lane, int wm, int wn) {
    const int g = lane >> 2, cl = (lane & 3) * 2;
    #pragma unroll
    for (int mt = 0; mt < 2; ++mt) {
        const int row0 = wm + mt * 16 + g;
        #pragma unroll
        for (int nt = 0; nt < 4; ++nt) {
            const int col = wn + nt * 8 + cl;
            float h0 = fmaxf(c[mt][nt][0] + sb[col],     0.f);
            float h1 = fmaxf(c[mt][nt][1] + sb[col + 1], 0.f);
            float h2 = fmaxf(c[mt][nt][2] + sb[col],     0.f);
            float h3 = fmaxf(c[mt][nt][3] + sb[col + 1], 0.f);
            uint32_t u0 = __float_as_uint(h0), u1 = __float_as_uint(h1);
            uint32_t u2 = __float_as_uint(h2), u3 = __float_as_uint(h3);
            uint32_t hi01, hi23, lo01, lo23;
            asm("prmt.b32 %0, %1, %2, 0x7632;" : "=r"(hi01) : "r"(u0), "r"(u1));
            asm("prmt.b32 %0, %1, %2, 0x7632;" : "=r"(hi23) : "r"(u2), "r"(u3));
            float r0 = h0 - __uint_as_float(u0 & 0xFFFF0000u);
            float r1 = h1 - __uint_as_float(u1 & 0xFFFF0000u);
            float r2 = h2 - __uint_as_float(u2 & 0xFFFF0000u);
            float r3 = h3 - __uint_as_float(u3 & 0xFFFF0000u);
            asm("cvt.rn.bf16x2.f32 %0, %1, %2;" : "=r"(lo01) : "f"(r1), "f"(r0));
            asm("cvt.rn.bf16x2.f32 %0, %1, %2;" : "=r"(lo23) : "f"(r3), "f"(r2));
            *reinterpret_cast<uint32_t*>(sAhi + row0 * 136 + col)       = hi01;
            *reinterpret_cast<uint32_t*>(sAlo + row0 * 136 + col)       = lo01;
            *reinterpret_cast<uint32_t*>(sAhi + (row0 + 8) * 136 + col) = hi23;
            *reinterpret_cast<uint32_t*>(sAlo + (row0 + 8) * 136 + col) = lo23;
        }
    }
}

// ---------------- fused message MLP: Y = mlp_m(x) (fp16 out) ----------------
__global__ __launch_bounds__(256, 2)
void msg_kernel(const float* __restrict__ x, const float* __restrict__ bm1,
                const float* __restrict__ bm2, __half* __restrict__ Y)
{
    extern __shared__ char smc[];
    float* sb1 = (float*)smc;            // 512
    float* sb2 = sb1 + 128;              // 512
    unsigned short* sAhi = (unsigned short*)(smc + 1024);
    unsigned short* sAlo = sAhi + 64 * 136;
    unsigned short* sBhi = sAlo + 64 * 136;
    unsigned short* sBlo = sBhi + 128 * 136;

    const int tid = threadIdx.x, lane = tid & 31, wid = tid >> 5;
    const int wm = (wid >> 2) * 32, wn = (wid & 3) * 32;
    const int m0 = blockIdx.x * 64;

    if (tid < 128) { sb1[tid] = bm1[tid]; sb2[tid] = bm2[tid]; }
    load_A_split(x + (size_t)m0 * D, sAhi, sAlo, tid);
    load_B(0, 128, 0, sBhi, sBlo, tid);
    __syncthreads();

    float c[2][4][4];
    zero_c(c);
    mma_chunk(sAhi, sAlo, sBhi, sBlo, c, lane, wm, wn);
    __syncthreads();                                  // everyone done reading tiles

    epi_split_to_sA(c, sb1, sAhi, sAlo, lane, wm, wn);  // H1 -> A tile (relu)
    load_B(16384, 128, 0, sBhi, sBlo, tid);             // Wm2
    __syncthreads();

    zero_c(c);
    mma_chunk(sAhi, sAlo, sBhi, sBlo, c, lane, wm, wn);

    const int g = lane >> 2, cl = (lane & 3) * 2;
    #pragma unroll
    for (int mt = 0; mt < 2; ++mt) {
        const int m = m0 + wm + mt * 16 + g;
        #pragma unroll
        for (int nt = 0; nt < 4; ++nt) {
            const int n = wn + nt * 8 + cl;
            float2 o0 = make_float2(c[mt][nt][0] + sb2[n], c[mt][nt][1] + sb2[n + 1]);
            float2 o1 = make_float2(c[mt][nt][2] + sb2[n], c[mt][nt][3] + sb2[n + 1]);
            *reinterpret_cast<__half2*>(Y + (size_t)m * D + n)       = __float22half2_rn(o0);
            *reinterpret_cast<__half2*>(Y + (size_t)(m + 8) * D + n) = __float22half2_rn(o1);
        }
    }
}

// ---------------- fused update MLP + residual + LayerNorm -------------------
__global__ __launch_bounds__(256, 2)
void upd_kernel(const float* __restrict__ x, const float* __restrict__ AGG,
                const float* __restrict__ bu1, const float* __restrict__ bu2,
                const float* __restrict__ gamma, const float* __restrict__ beta,
                float* __restrict__ out)
{
    extern __shared__ char smc[];
    float* sb1  = (float*)smc;           // 512
    float* sb2  = sb1 + 128;
    float* sg   = sb2 + 128;
    float* sbt  = sg + 128;
    float* ssum = sbt + 128;             // 64 floats
    float* ssq  = ssum + 64;             // 64 floats
    unsigned short* sAhi = (unsigned short*)(smc + 2560);
    unsigned short* sAlo = sAhi + 64 * 136;
    unsigned short* sBhi = sAlo + 64 * 136;
    unsigned short* sBlo = sBhi + 128 * 136;

    const int tid = threadIdx.x, lane = tid & 31, wid = tid >> 5;
    const int wm = (wid >> 2) * 32, wn = (wid & 3) * 32;
    const int m0 = blockIdx.x * 64;

    if (tid < 128) {
        sb1[tid] = bu1[tid]; sb2[tid] = bu2[tid];
        sg[tid] = gamma[tid]; sbt[tid] = beta[tid];
        if (tid < 64) { ssum[tid] = 0.f; ssq[tid] = 0.f; }
    }

    float c[2][4][4];
    zero_c(c);

    // K chunk 0: x part of concat
    load_A_split(x + (size_t)m0 * D, sAhi, sAlo, tid);
    load_B(32768, 256, 0, sBhi, sBlo, tid);
    __syncthreads();
    mma_chunk(sAhi, sAlo, sBhi, sBlo, c, lane, wm, wn);
    __syncthreads();
    // K chunk 1: AGG part of concat
    load_A_split(AGG + (size_t)m0 * D, sAhi, sAlo, tid);
    load_B(32768, 256, 1, sBhi, sBlo, tid);
    __syncthreads();
    mma_chunk(sAhi, sAlo, sBhi, sBlo, c, lane, wm, wn);
    __syncthreads();

    epi_split_to_sA(c, sb1, sAhi, sAlo, lane, wm, wn);  // U1 -> A tile (relu)
    load_B(65536, 128, 0, sBhi, sBlo, tid);             // Wu2
    __syncthreads();

    zero_c(c);
    mma_chunk(sAhi, sAlo, sBhi, sBlo, c, lane, wm, wn);
    __syncthreads();

    // h = c + bias + residual(x); keep in c. Row partial sums -> smem.
    const int g = lane >> 2, cl = (lane & 3) * 2;
    #pragma unroll
    for (int mt = 0; mt < 2; ++mt) {
        const int row0 = wm + mt * 16 + g;
        float s0 = 0.f, q0 = 0.f, s1 = 0.f, q1 = 0.f;
        #pragma unroll
        for (int nt = 0; nt < 4; ++nt) {
            const int col = wn + nt * 8 + cl;
            float2 r0 = *reinterpret_cast<const float2*>(x + (size_t)(m0 + row0) * D + col);
            float2 r1 = *reinterpret_cast<const float2*>(x + (size_t)(m0 + row0 + 8) * D + col);
            float h0 = c[mt][nt][0] + sb2[col]     + r0.x;
            float h1 = c[mt][nt][1] + sb2[col + 1] + r0.y;
            float h2 = c[mt][nt][2] + sb2[col]     + r1.x;
            float h3 = c[mt][nt][3] + sb2[col + 1] + r1.y;
            c[mt][nt][0] = h0; c[mt][nt][1] = h1; c[mt][nt][2] = h2; c[mt][nt][3] = h3;
            s0 += h0 + h1; q0 += h0 * h0 + h1 * h1;
            s1 += h2 + h3; q1 += h2 * h2 + h3 * h3;
        }
        #pragma unroll
        for (int o = 1; o <= 2; o <<= 1) {
            s0 += __shfl_xor_sync(0xffffffffu, s0, o);
            q0 += __shfl_xor_sync(0xffffffffu, q0, o);
            s1 += __shfl_xor_sync(0xffffffffu, s1, o);
            q1 += __shfl_xor_sync(0xffffffffu, q1, o);
        }
        if ((lane & 3) == 0) {
            atomicAdd(&ssum[row0], s0);     atomicAdd(&ssq[row0], q0);
            atomicAdd(&ssum[row0 + 8], s1); atomicAdd(&ssq[row0 + 8], q1);
        }
    }
    __syncthreads();

    #pragma unroll
    for (int mt = 0; mt < 2; ++mt) {
        const int row0 = wm + mt * 16 + g;
        float mu0 = ssum[row0] * (1.f / 128.f);
        float v0  = ssq[row0] * (1.f / 128.f) - mu0 * mu0;
        float rs0 = rsqrtf(v0 + 1e-5f);
        float mu1 = ssum[row0 + 8] * (1.f / 128.f);
        float v1  = ssq[row0 + 8] * (1.f / 128.f) - mu1 * mu1;
        float rs1 = rsqrtf(v1 + 1e-5f);
        #pragma unroll
        for (int nt = 0; nt < 4; ++nt) {
            const int col = wn + nt * 8 + cl;
            float2 o0, o1;
            o0.x = (c[mt][nt][0] - mu0) * rs0 * sg[col]     + sbt[col];
            o0.y = (c[mt][nt][1] - mu0) * rs0 * sg[col + 1] + sbt[col + 1];
            o1.x = (c[mt][nt][2] - mu1) * rs1 * sg[col]     + sbt[col];
            o1.y = (c[mt][nt][3] - mu1) * rs1 * sg[col + 1] + sbt[col + 1];
            *reinterpret_cast<float2*>(out + (size_t)(m0 + row0) * D + col)     = o0;
            *reinterpret_cast<float2*>(out + (size_t)(m0 + row0 + 8) * D + col) = o1;
        }
    }
}

// ---------------- weight pre-split -------------------------------------------
__global__ void wsplit_kernel(const float* __restrict__ Wm1, const float* __restrict__ Wm2,
                              const float* __restrict__ Wu1, const float* __restrict__ Wu2)
{
    int i = blockIdx.x * blockDim.x + threadIdx.x;
    if (i >= 81920) return;
    float f;
    if      (i < 16384) f = Wm1[i];
    else if (i < 32768) f = Wm2[i - 16384];
    else if (i < 65536) f = Wu1[i - 32768];
    else                f = Wu2[i - 65536];
    uint32_t u = __float_as_uint(f);
    g_Wh[i] = (unsigned short)(u >> 16);
    float lo = f - __uint_as_float(u & 0xFFFF0000u);
    g_Wl[i] = __bfloat16_as_ushort(__float2bfloat16(lo));
}

// ---------------- edge dtype sniff -------------------------------------------
__global__ void detect_kernel(const int* __restrict__ e) {
    if (threadIdx.x == 0) {
        int any = 0;
        for (int i = 1; i < 256; i += 2) any |= e[i];
        g_is64 = (any == 0) ? 1 : 0;
    }
}

// ---------------- CSR build (scatter-mean without float atomics) ------------
__global__ void zero_cur_kernel(int* __restrict__ CUR) {
    int i = blockIdx.x * blockDim.x + threadIdx.x;
    if (i < N_NODES) CUR[i] = 0;
}
__global__ void count_kernel(const void* __restrict__ eidx, int* __restrict__ CUR) {
    int e = blockIdx.x * blockDim.x + threadIdx.x;     // 2500*256 = E exact
    int dst = g_is64 ? (int)reinterpret_cast<const long long*>(eidx)[N_EDGES + e]
                     : reinterpret_cast<const int*>(eidx)[N_EDGES + e];
    atomicAdd(&CUR[dst], 1);
}
__global__ void scan_kernel(int* __restrict__ CUR, int* __restrict__ ROW) {
    __shared__ int bs[1024];
    const int t = threadIdx.x;
    const int base = t * 40;
    int s = 0;
    for (int i = 0; i < 40; i++) {
        int idx = base + i;
        if (idx < N_NODES) s += CUR[idx];
    }
    bs[t] = s;
    __syncthreads();
    for (int off = 1; off < 1024; off <<= 1) {
        int v = (t >= off) ? bs[t - off] : 0;
        __syncthreads();
        bs[t] += v;
        __syncthreads();
    }
    int run = (t == 0) ? 0 : bs[t - 1];
    for (int i = 0; i < 40; i++) {
        int idx = base + i;
        if (idx < N_NODES) {
            int cv = CUR[idx];
            ROW[idx] = run;
            CUR[idx] = run;       // cursor for fill
            run += cv;
        }
    }
    if (t == 0) ROW[N_NODES] = N_EDGES;
}
__global__ void fill_kernel(const void* __restrict__ eidx, int* __restrict__ CUR,
                            int* __restrict__ EIDX) {
    int e = blockIdx.x * blockDim.x + threadIdx.x;
    int src, dst;
    if (g_is64) {
        const long long* p = reinterpret_cast<const long long*>(eidx);
        src = (int)p[e]; dst = (int)p[N_EDGES + e];
    } else {
        const int* p = reinterpret_cast<const int*>(eidx);
        src = p[e]; dst = p[N_EDGES + e];
    }
    int pos = atomicAdd(&CUR[dst], 1);
    EIDX[pos] = src;
}
// one warp per node: sum fp16 Y[src] over incoming edges, divide by degree
__global__ void gather_kernel(const __half* __restrict__ Y, const int* __restrict__ ROW,
                              const int* __restrict__ EIDX, float* __restrict__ AGG) {
    const int n    = blockIdx.x * 8 + (threadIdx.x >> 5);
    const int lane = threadIdx.x & 31;
    const int s = ROW[n], e = ROW[n + 1];
    float4 acc = make_float4(0.f, 0.f, 0.f, 0.f);
    for (int base = s; base < e; base += 32) {
        const int cnt = min(32, e - base);
        int idx = (base + lane < e) ? EIDX[base + lane] : 0;
        for (int j = 0; j < cnt; j++) {
            int src = __shfl_sync(0xffffffffu, idx, j);
            // 4 halves per lane: cols lane*4 .. lane*4+3 (8B load)
            __half2 h01 = reinterpret_cast<const __half2*>(Y + (size_t)src * D)[lane * 2];
            __half2 h23 = reinterpret_cast<const __half2*>(Y + (size_t)src * D)[lane * 2 + 1];
            float2 f01 = __half22float2(h01);
            float2 f23 = __half22float2(h23);
            acc.x += f01.x; acc.y += f01.y; acc.z += f23.x; acc.w += f23.y;
        }
    }
    const float sc = 1.0f / (float)max(e - s, 1);
    acc.x *= sc; acc.y *= sc; acc.z *= sc; acc.w *= sc;
    reinterpret_cast<float4*>(AGG + (size_t)n * D)[lane] = acc;
}

// ---------------- launch -----------------------------------------------------
extern "C" void kernel_launch(void* const* d_in, const int* in_sizes, int n_in,
                              void* d_out, int out_size)
{
    const float* x     = (const float*)d_in[0];
    const void*  eidx  =               d_in[1];
    const float* Wm1   = (const float*)d_in[2];
    const float* bm1   = (const float*)d_in[3];
    const float* Wm2   = (const float*)d_in[4];
    const float* bm2   = (const float*)d_in[5];
    const float* Wu1   = (const float*)d_in[6];
    const float* bu1   = (const float*)d_in[7];
    const float* Wu2   = (const float*)d_in[8];
    const float* bu2   = (const float*)d_in[9];
    const float* gamma = (const float*)d_in[10];
    const float* beta  = (const float*)d_in[11];
    float* out = (float*)d_out;

    void *pY, *pAGG, *pROW, *pCUR, *pEIDX;
    cudaGetSymbolAddress(&pY,    g_Y);
    cudaGetSymbolAddress(&pAGG,  g_AGG);
    cudaGetSymbolAddress(&pROW,  g_ROW);
    cudaGetSymbolAddress(&pCUR,  g_CUR);
    cudaGetSymbolAddress(&pEIDX, g_EIDX);

    // smem: hdr + A hi/lo (64x136) + B hi/lo (128x136), shorts
    const int SM1 = 1024 + 2 * (64 * 136 * 2) + 2 * (128 * 136 * 2);  // 105472
    const int SM2 = 2560 + 2 * (64 * 136 * 2) + 2 * (128 * 136 * 2);  // 107008
    cudaFuncSetAttribute(msg_kernel, cudaFuncAttributeMaxDynamicSharedMemorySize, SM1);
    cudaFuncSetAttribute(upd_kernel, cudaFuncAttributeMaxDynamicSharedMemorySize, SM2);

    detect_kernel  <<<1, 32>>>((const int*)eidx);
    wsplit_kernel  <<<320, 256>>>(Wm1, Wm2, Wu1, Wu2);
    zero_cur_kernel<<<157, 256>>>((int*)pCUR);
    count_kernel   <<<2500, 256>>>(eidx, (int*)pCUR);
    scan_kernel    <<<1, 1024>>>((int*)pCUR, (int*)pROW);
    fill_kernel    <<<2500, 256>>>(eidx, (int*)pCUR, (int*)pEIDX);

    // fused message MLP (per-node, algebraically identical to per-edge)
    msg_kernel<<<625, 256, SM1>>>(x, bm1, bm2, (__half*)pY);
    // CSR gather-mean over fp16 Y
    gather_kernel<<<5000, 256>>>((const __half*)pY, (const int*)pROW,
                                 (const int*)pEIDX, (float*)pAGG);
    // fused update MLP + residual + LayerNorm
    upd_kernel<<<625, 256, SM2>>>(x, (const float*)pAGG, bu1, bu2, gamma, beta, out);
}

// round 12
// speedup vs baseline: 1.0442x; 1.0009x over previous
#include <cuda_runtime.h>
#include <cuda_bf16.h>
#include <cuda_fp16.h>
#include <cstdint>

#define N_NODES 40000
#define N_EDGES 640000
#define D 128

// ---------------- scratch (device globals: no allocations allowed) ----------
static __device__ __half g_Y [N_NODES * D];   // per-node message output (fp16)
static __device__ float g_AGG[N_NODES * D];   // scatter-mean result
static __device__ int   g_ROW[N_NODES + 1];   // CSR row offsets (by dst)
static __device__ int   g_CUR[N_NODES];       // counts, then fill cursors
static __device__ int   g_EIDX[N_EDGES];      // src ids grouped by dst
static __device__ int   g_is64;               // edge_index dtype flag
// pre-split weights (bf16 hi / lo), [n][k] row-major:
//   Wm1 @ 0 (16384), Wm2 @ 16384, Wu1 @ 32768 (32768), Wu2 @ 65536
static __device__ unsigned short g_Wh[81920];
static __device__ unsigned short g_Wl[81920];

// ---------------- helpers ----------------------------------------------------
__device__ __forceinline__ uint32_t smem_u32(const void* p) {
    return (uint32_t)__cvta_generic_to_shared(p);
}

// split 4 fp32 -> bf16 hi (truncate) pairs + bf16 lo (rn of residual) pairs
__device__ __forceinline__ void split4(float4 v, uint32_t& h01, uint32_t& h23,
                                       uint32_t& l01, uint32_t& l23) {
    uint32_t u0 = __float_as_uint(v.x), u1 = __float_as_uint(v.y);
    uint32_t u2 = __float_as_uint(v.z), u3 = __float_as_uint(v.w);
    asm("prmt.b32 %0, %1, %2, 0x7632;" : "=r"(h01) : "r"(u0), "r"(u1));
    asm("prmt.b32 %0, %1, %2, 0x7632;" : "=r"(h23) : "r"(u2), "r"(u3));
    float lo0 = v.x - __uint_as_float(u0 & 0xFFFF0000u);
    float lo1 = v.y - __uint_as_float(u1 & 0xFFFF0000u);
    float lo2 = v.z - __uint_as_float(u2 & 0xFFFF0000u);
    float lo3 = v.w - __uint_as_float(u3 & 0xFFFF0000u);
    asm("cvt.rn.bf16x2.f32 %0, %1, %2;" : "=r"(l01) : "f"(lo1), "f"(lo0));
    asm("cvt.rn.bf16x2.f32 %0, %1, %2;" : "=r"(l23) : "f"(lo3), "f"(lo2));
}

#define LDSM_X4(r0, r1, r2, r3, addr) \
    asm volatile("ldmatrix.sync.aligned.m8n8.x4.shared.b16 {%0,%1,%2,%3}, [%4];" \
        : "=r"(r0), "=r"(r1), "=r"(r2), "=r"(r3) : "r"(addr))

#define MMA_BF16(c, a, b) \
    asm volatile("mma.sync.aligned.m16n8k16.row.col.f32.bf16.bf16.f32 " \
        "{%0,%1,%2,%3}, {%4,%5,%6,%7}, {%8,%9}, {%0,%1,%2,%3};" \
        : "+f"((c)[0]), "+f"((c)[1]), "+f"((c)[2]), "+f"((c)[3]) \
        : "r"((a)[0]), "r"((a)[1]), "r"((a)[2]), "r"((a)[3]), \
          "r"((b)[0]), "r"((b)[1]))

// ---- shared GEMM building blocks (tile M=64 x N=128, K-chunk 128) ----------
__device__ __forceinline__ void load_A_split(const float* __restrict__ Asrc,
                                             unsigned short* sAhi, unsigned short* sAlo,
                                             int tid) {
    #pragma unroll
    for (int it = 0; it < 8; ++it) {
        int idx  = tid + it * 256;
        int row  = idx >> 5;
        int col4 = idx & 31;
        float4 v = *reinterpret_cast<const float4*>(Asrc + (size_t)row * D + col4 * 4);
        uint32_t h01, h23, l01, l23;
        split4(v, h01, h23, l01, l23);
        *reinterpret_cast<uint2*>(sAhi + row * 136 + col4 * 4) = make_uint2(h01, h23);
        *reinterpret_cast<uint2*>(sAlo + row * 136 + col4 * 4) = make_uint2(l01, l23);
    }
}
__device__ __forceinline__ void load_B(int woff, int kstride, int kc,
                                       unsigned short* sBhi, unsigned short* sBlo,
                                       int tid) {
    #pragma unroll
    for (int it = 0; it < 8; ++it) {
        int idx = tid + it * 256;
        int row = idx >> 4;
        int c8  = idx & 15;
        size_t gsrc = (size_t)woff + (size_t)row * kstride + kc * 128 + c8 * 8;
        *reinterpret_cast<uint4*>(sBhi + row * 136 + c8 * 8) =
            *reinterpret_cast<const uint4*>(g_Wh + gsrc);
        *reinterpret_cast<uint4*>(sBlo + row * 136 + c8 * 8) =
            *reinterpret_cast<const uint4*>(g_Wl + gsrc);
    }
}
__device__ __forceinline__ void mma_chunk(const unsigned short* sAhi, const unsigned short* sAlo,
                                          const unsigned short* sBhi, const unsigned short* sBlo,
                                          float c[2][4][4], int lane, int wm, int wn) {
    const int a_row = lane & 15, a_kh = (lane >> 4) * 8;
    const int b_row = (lane >> 4) * 8 + (lane & 7);
    const int b_kh  = ((lane >> 3) & 1) * 8;
    #pragma unroll
    for (int ks = 0; ks < 8; ++ks) {
        const int kb = ks * 16;
        uint32_t ah[2][4], al[2][4], bh[4][2], bl[4][2];
        #pragma unroll
        for (int mt = 0; mt < 2; ++mt) {
            uint32_t addr = smem_u32(sAhi + (wm + mt * 16 + a_row) * 136 + kb + a_kh);
            LDSM_X4(ah[mt][0], ah[mt][1], ah[mt][2], ah[mt][3], addr);
            addr = smem_u32(sAlo + (wm + mt * 16 + a_row) * 136 + kb + a_kh);
            LDSM_X4(al[mt][0], al[mt][1], al[mt][2], al[mt][3], addr);
        }
        #pragma unroll
        for (int bt = 0; bt < 2; ++bt) {
            uint32_t addr = smem_u32(sBhi + (wn + bt * 16 + b_row) * 136 + kb + b_kh);
            LDSM_X4(bh[bt*2][0], bh[bt*2][1], bh[bt*2+1][0], bh[bt*2+1][1], addr);
            addr = smem_u32(sBlo + (wn + bt * 16 + b_row) * 136 + kb + b_kh);
            LDSM_X4(bl[bt*2][0], bl[bt*2][1], bl[bt*2+1][0], bl[bt*2+1][1], addr);
        }
        #pragma unroll
        for (int mt = 0; mt < 2; ++mt)
            #pragma unroll
            for (int nt = 0; nt < 4; ++nt) {
                MMA_BF16(c[mt][nt], ah[mt], bh[nt]);
                MMA_BF16(c[mt][nt], ah[mt], bl[nt]);
                MMA_BF16(c[mt][nt], al[mt], bh[nt]);
            }
    }
}
__device__ __forceinline__ void zero_c(float c[2][4][4]) {
    #pragma unroll
    for (int i = 0; i < 2; i++)
        #pragma unroll
        for (int j = 0; j < 4; j++)
            #pragma unroll
            for (int q = 0; q < 4; q++) c[i][j][q] = 0.0f;
}
// bias(+relu) the accumulators, split to bf16 hi/lo, write as next A tile
__device__ __forceinline__ void epi_split_to_sA(float c[2][4][4], const float* sb,
                                                unsigned short* sAhi, unsigned short* sAlo,
                                                int lane, int wm, int wn) {
    const int g = lane >> 2, cl = (lane & 3) * 2;
    #pragma unroll
    for (int mt = 0; mt < 2; ++mt) {
        const int row0 = wm + mt * 16 + g;
        #pragma unroll
        for (int nt = 0; nt < 4; ++nt) {
            const int col = wn + nt * 8 + cl;
            float h0 = fmaxf(c[mt][nt][0] + sb[col],     0.f);
            float h1 = fmaxf(c[mt][nt][1] + sb[col + 1], 0.f);
            float h2 = fmaxf(c[mt][nt][2] + sb[col],     0.f);
            float h3 = fmaxf(c[mt][nt][3] + sb[col + 1], 0.f);
            uint32_t u0 = __float_as_uint(h0), u1 = __float_as_uint(h1);
            uint32_t u2 = __float_as_uint(h2), u3 = __float_as_uint(h3);
            uint32_t hi01, hi23, lo01, lo23;
            asm("prmt.b32 %0, %1, %2, 0x7632;" : "=r"(hi01) : "r"(u0), "r"(u1));
            asm("prmt.b32 %0, %1, %2, 0x7632;" : "=r"(hi23) : "r"(u2), "r"(u3));
            float r0 = h0 - __uint_as_float(u0 & 0xFFFF0000u);
            float r1 = h1 - __uint_as_float(u1 & 0xFFFF0000u);
            float r2 = h2 - __uint_as_float(u2 & 0xFFFF0000u);
            float r3 = h3 - __uint_as_float(u3 & 0xFFFF0000u);
            asm("cvt.rn.bf16x2.f32 %0, %1, %2;" : "=r"(lo01) : "f"(r1), "f"(r0));
            asm("cvt.rn.bf16x2.f32 %0, %1, %2;" : "=r"(lo23) : "f"(r3), "f"(r2));
            *reinterpret_cast<uint32_t*>(sAhi + row0 * 136 + col)       = hi01;
            *reinterpret_cast<uint32_t*>(sAlo + row0 * 136 + col)       = lo01;
            *reinterpret_cast<uint32_t*>(sAhi + (row0 + 8) * 136 + col) = hi23;
            *reinterpret_cast<uint32_t*>(sAlo + (row0 + 8) * 136 + col) = lo23;
        }
    }
}

// ---------------- fused message MLP: Y = mlp_m(x) (fp16 out) ----------------
__global__ __launch_bounds__(256, 2)
void msg_kernel(const float* __restrict__ x, const float* __restrict__ bm1,
                const float* __restrict__ bm2, __half* __restrict__ Y)
{
    extern __shared__ char smc[];
    float* sb1 = (float*)smc;            // 512
    float* sb2 = sb1 + 128;              // 512
    unsigned short* sAhi = (unsigned short*)(smc + 1024);
    unsigned short* sAlo = sAhi + 64 * 136;
    unsigned short* sBhi = sAlo + 64 * 136;
    unsigned short* sBlo = sBhi + 128 * 136;

    const int tid = threadIdx.x, lane = tid & 31, wid = tid >> 5;
    const int wm = (wid >> 2) * 32, wn = (wid & 3) * 32;
    const int m0 = blockIdx.x * 64;

    if (tid < 128) { sb1[tid] = bm1[tid]; sb2[tid] = bm2[tid]; }
    load_A_split(x + (size_t)m0 * D, sAhi, sAlo, tid);
    load_B(0, 128, 0, sBhi, sBlo, tid);
    __syncthreads();

    float c[2][4][4];
    zero_c(c);
    mma_chunk(sAhi, sAlo, sBhi, sBlo, c, lane, wm, wn);
    __syncthreads();                                  // everyone done reading tiles

    epi_split_to_sA(c, sb1, sAhi, sAlo, lane, wm, wn);  // H1 -> A tile (relu)
    load_B(16384, 128, 0, sBhi, sBlo, tid);             // Wm2
    __syncthreads();

    zero_c(c);
    mma_chunk(sAhi, sAlo, sBhi, sBlo, c, lane, wm, wn);

    const int g = lane >> 2, cl = (lane & 3) * 2;
    #pragma unroll
    for (int mt = 0; mt < 2; ++mt) {
        const int m = m0 + wm + mt * 16 + g;
        #pragma unroll
        for (int nt = 0; nt < 4; ++nt) {
            const int n = wn + nt * 8 + cl;
            float2 o0 = make_float2(c[mt][nt][0] + sb2[n], c[mt][nt][1] + sb2[n + 1]);
            float2 o1 = make_float2(c[mt][nt][2] + sb2[n], c[mt][nt][3] + sb2[n + 1]);
            *reinterpret_cast<__half2*>(Y + (size_t)m * D + n)       = __float22half2_rn(o0);
            *reinterpret_cast<__half2*>(Y + (size_t)(m + 8) * D + n) = __float22half2_rn(o1);
        }
    }
}

// ---------------- fused update MLP + residual + LayerNorm -------------------
__global__ __launch_bounds__(256, 2)
void upd_kernel(const float* __restrict__ x, const float* __restrict__ AGG,
                const float* __restrict__ bu1, const float* __restrict__ bu2,
                const float* __restrict__ gamma, const float* __restrict__ beta,
                float* __restrict__ out)
{
    extern __shared__ char smc[];
    float* sb1  = (float*)smc;           // 512
    float* sb2  = sb1 + 128;
    float* sg   = sb2 + 128;
    float* sbt  = sg + 128;
    float* ssum = sbt + 128;             // 64 floats
    float* ssq  = ssum + 64;             // 64 floats
    unsigned short* sAhi = (unsigned short*)(smc + 2560);
    unsigned short* sAlo = sAhi + 64 * 136;
    unsigned short* sBhi = sAlo + 64 * 136;
    unsigned short* sBlo = sBhi + 128 * 136;

    const int tid = threadIdx.x, lane = tid & 31, wid = tid >> 5;
    const int wm = (wid >> 2) * 32, wn = (wid & 3) * 32;
    const int m0 = blockIdx.x * 64;

    if (tid < 128) {
        sb1[tid] = bu1[tid]; sb2[tid] = bu2[tid];
        sg[tid] = gamma[tid]; sbt[tid] = beta[tid];
        if (tid < 64) { ssum[tid] = 0.f; ssq[tid] = 0.f; }
    }

    float c[2][4][4];
    zero_c(c);

    // K chunk 0: x part of concat
    load_A_split(x + (size_t)m0 * D, sAhi, sAlo, tid);
    load_B(32768, 256, 0, sBhi, sBlo, tid);
    __syncthreads();
    mma_chunk(sAhi, sAlo, sBhi, sBlo, c, lane, wm, wn);
    __syncthreads();
    // K chunk 1: AGG part of concat
    load_A_split(AGG + (size_t)m0 * D, sAhi, sAlo, tid);
    load_B(32768, 256, 1, sBhi, sBlo, tid);
    __syncthreads();
    mma_chunk(sAhi, sAlo, sBhi, sBlo, c, lane, wm, wn);
    __syncthreads();

    epi_split_to_sA(c, sb1, sAhi, sAlo, lane, wm, wn);  // U1 -> A tile (relu)
    load_B(65536, 128, 0, sBhi, sBlo, tid);             // Wu2
    __syncthreads();

    zero_c(c);
    mma_chunk(sAhi, sAlo, sBhi, sBlo, c, lane, wm, wn);
    __syncthreads();

    // h = c + bias + residual(x); keep in c. Row partial sums -> smem.
    const int g = lane >> 2, cl = (lane & 3) * 2;
    #pragma unroll
    for (int mt = 0; mt < 2; ++mt) {
        const int row0 = wm + mt * 16 + g;
        float s0 = 0.f, q0 = 0.f, s1 = 0.f, q1 = 0.f;
        #pragma unroll
        for (int nt = 0; nt < 4; ++nt) {
            const int col = wn + nt * 8 + cl;
            float2 r0 = *reinterpret_cast<const float2*>(x + (size_t)(m0 + row0) * D + col);
            float2 r1 = *reinterpret_cast<const float2*>(x + (size_t)(m0 + row0 + 8) * D + col);
            float h0 = c[mt][nt][0] + sb2[col]     + r0.x;
            float h1 = c[mt][nt][1] + sb2[col + 1] + r0.y;
            float h2 = c[mt][nt][2] + sb2[col]     + r1.x;
            float h3 = c[mt][nt][3] + sb2[col + 1] + r1.y;
            c[mt][nt][0] = h0; c[mt][nt][1] = h1; c[mt][nt][2] = h2; c[mt][nt][3] = h3;
            s0 += h0 + h1; q0 += h0 * h0 + h1 * h1;
            s1 += h2 + h3; q1 += h2 * h2 + h3 * h3;
        }
        #pragma unroll
        for (int o = 1; o <= 2; o <<= 1) {
            s0 += __shfl_xor_sync(0xffffffffu, s0, o);
            q0 += __shfl_xor_sync(0xffffffffu, q0, o);
            s1 += __shfl_xor_sync(0xffffffffu, s1, o);
            q1 += __shfl_xor_sync(0xffffffffu, q1, o);
        }
        if ((lane & 3) == 0) {
            atomicAdd(&ssum[row0], s0);     atomicAdd(&ssq[row0], q0);
            atomicAdd(&ssum[row0 + 8], s1); atomicAdd(&ssq[row0 + 8], q1);
        }
    }
    __syncthreads();

    #pragma unroll
    for (int mt = 0; mt < 2; ++mt) {
        const int row0 = wm + mt * 16 + g;
        float mu0 = ssum[row0] * (1.f / 128.f);
        float v0  = ssq[row0] * (1.f / 128.f) - mu0 * mu0;
        float rs0 = rsqrtf(v0 + 1e-5f);
        float mu1 = ssum[row0 + 8] * (1.f / 128.f);
        float v1  = ssq[row0 + 8] * (1.f / 128.f) - mu1 * mu1;
        float rs1 = rsqrtf(v1 + 1e-5f);
        #pragma unroll
        for (int nt = 0; nt < 4; ++nt) {
            const int col = wn + nt * 8 + cl;
            float2 o0, o1;
            o0.x = (c[mt][nt][0] - mu0) * rs0 * sg[col]     + sbt[col];
            o0.y = (c[mt][nt][1] - mu0) * rs0 * sg[col + 1] + sbt[col + 1];
            o1.x = (c[mt][nt][2] - mu1) * rs1 * sg[col]     + sbt[col];
            o1.y = (c[mt][nt][3] - mu1) * rs1 * sg[col + 1] + sbt[col + 1];
            *reinterpret_cast<float2*>(out + (size_t)(m0 + row0) * D + col)     = o0;
            *reinterpret_cast<float2*>(out + (size_t)(m0 + row0 + 8) * D + col) = o1;
        }
    }
}

// ---------------- weight pre-split -------------------------------------------
__global__ void wsplit_kernel(const float* __restrict__ Wm1, const float* __restrict__ Wm2,
                              const float* __restrict__ Wu1, const float* __restrict__ Wu2)
{
    int i = blockIdx.x * blockDim.x + threadIdx.x;
    if (i >= 81920) return;
    float f;
    if      (i < 16384) f = Wm1[i];
    else if (i < 32768) f = Wm2[i - 16384];
    else if (i < 65536) f = Wu1[i - 32768];
    else                f = Wu2[i - 65536];
    uint32_t u = __float_as_uint(f);
    g_Wh[i] = (unsigned short)(u >> 16);
    float lo = f - __uint_as_float(u & 0xFFFF0000u);
    g_Wl[i] = __bfloat16_as_ushort(__float2bfloat16(lo));
}

// ---------------- edge dtype sniff -------------------------------------------
__global__ void detect_kernel(const int* __restrict__ e) {
    if (threadIdx.x == 0) {
        int any = 0;
        for (int i = 1; i < 256; i += 2) any |= e[i];
        g_is64 = (any == 0) ? 1 : 0;
    }
}

// ---------------- CSR build (scatter-mean without float atomics) ------------
__global__ void zero_cur_kernel(int* __restrict__ CUR) {
    int i = blockIdx.x * blockDim.x + threadIdx.x;
    if (i < N_NODES) CUR[i] = 0;
}
__global__ void count_kernel(const void* __restrict__ eidx, int* __restrict__ CUR) {
    int e = blockIdx.x * blockDim.x + threadIdx.x;     // 2500*256 = E exact
    int dst = g_is64 ? (int)reinterpret_cast<const long long*>(eidx)[N_EDGES + e]
                     : reinterpret_cast<const int*>(eidx)[N_EDGES + e];
    atomicAdd(&CUR[dst], 1);
}
__global__ void scan_kernel(int* __restrict__ CUR, int* __restrict__ ROW) {
    __shared__ int bs[1024];
    const int t = threadIdx.x;
    const int base = t * 40;
    int s = 0;
    for (int i = 0; i < 40; i++) {
        int idx = base + i;
        if (idx < N_NODES) s += CUR[idx];
    }
    bs[t] = s;
    __syncthreads();
    for (int off = 1; off < 1024; off <<= 1) {
        int v = (t >= off) ? bs[t - off] : 0;
        __syncthreads();
        bs[t] += v;
        __syncthreads();
    }
    int run = (t == 0) ? 0 : bs[t - 1];
    for (int i = 0; i < 40; i++) {
        int idx = base + i;
        if (idx < N_NODES) {
            int cv = CUR[idx];
            ROW[idx] = run;
            CUR[idx] = run;       // cursor for fill
            run += cv;
        }
    }
    if (t == 0) ROW[N_NODES] = N_EDGES;
}
__global__ void fill_kernel(const void* __restrict__ eidx, int* __restrict__ CUR,
                            int* __restrict__ EIDX) {
    int e = blockIdx.x * blockDim.x + threadIdx.x;
    int src, dst;
    if (g_is64) {
        const long long* p = reinterpret_cast<const long long*>(eidx);
        src = (int)p[e]; dst = (int)p[N_EDGES + e];
    } else {
        const int* p = reinterpret_cast<const int*>(eidx);
        src = p[e]; dst = p[N_EDGES + e];
    }
    int pos = atomicAdd(&CUR[dst], 1);
    EIDX[pos] = src;
}
// one warp per node: sum fp16 Y[src] over incoming edges, divide by degree.
// 4-deep edge unroll with 4 independent accumulators -> ~8 loads in flight
// instead of 1 (the gather was latency-bound, not bandwidth-bound).
__global__ void gather_kernel(const __half* __restrict__ Y, const int* __restrict__ ROW,
                              const int* __restrict__ EIDX, float* __restrict__ AGG) {
    const int n    = blockIdx.x * 8 + (threadIdx.x >> 5);
    const int lane = threadIdx.x & 31;
    const int s = ROW[n], e = ROW[n + 1];
    float4 a0 = make_float4(0.f, 0.f, 0.f, 0.f);
    float4 a1 = make_float4(0.f, 0.f, 0.f, 0.f);
    float4 a2 = make_float4(0.f, 0.f, 0.f, 0.f);
    float4 a3 = make_float4(0.f, 0.f, 0.f, 0.f);
    for (int base = s; base < e; base += 32) {
        const int cnt = min(32, e - base);
        int idx = (base + lane < e) ? EIDX[base + lane] : 0;
        int j = 0;
        for (; j + 4 <= cnt; j += 4) {
            int s0 = __shfl_sync(0xffffffffu, idx, j);
            int s1 = __shfl_sync(0xffffffffu, idx, j + 1);
            int s2 = __shfl_sync(0xffffffffu, idx, j + 2);
            int s3 = __shfl_sync(0xffffffffu, idx, j + 3);
            // 8 independent 8B loads issued before any consuming add
            uint2 r0 = *reinterpret_cast<const uint2*>(Y + (size_t)s0 * D + lane * 4);
            uint2 r1 = *reinterpret_cast<const uint2*>(Y + (size_t)s1 * D + lane * 4);
            uint2 r2 = *reinterpret_cast<const uint2*>(Y + (size_t)s2 * D + lane * 4);
            uint2 r3 = *reinterpret_cast<const uint2*>(Y + (size_t)s3 * D + lane * 4);
            float2 f;
            f = __half22float2(*(__half2*)&r0.x); a0.x += f.x; a0.y += f.y;
            f = __half22float2(*(__half2*)&r0.y); a0.z += f.x; a0.w += f.y;
            f = __half22float2(*(__half2*)&r1.x); a1.x += f.x; a1.y += f.y;
            f = __half22float2(*(__half2*)&r1.y); a1.z += f.x; a1.w += f.y;
            f = __half22float2(*(__half2*)&r2.x); a2.x += f.x; a2.y += f.y;
            f = __half22float2(*(__half2*)&r2.y); a2.z += f.x; a2.w += f.y;
            f = __half22float2(*(__half2*)&r3.x); a3.x += f.x; a3.y += f.y;
            f = __half22float2(*(__half2*)&r3.y); a3.z += f.x; a3.w += f.y;
        }
        for (; j < cnt; ++j) {
            int s0 = __shfl_sync(0xffffffffu, idx, j);
            uint2 r0 = *reinterpret_cast<const uint2*>(Y + (size_t)s0 * D + lane * 4);
            float2 f;
            f = __half22float2(*(__half2*)&r0.x); a0.x += f.x; a0.y += f.y;
            f = __half22float2(*(__half2*)&r0.y); a0.z += f.x; a0.w += f.y;
        }
    }
    float4 acc;
    acc.x = (a0.x + a1.x) + (a2.x + a3.x);
    acc.y = (a0.y + a1.y) + (a2.y + a3.y);
    acc.z = (a0.z + a1.z) + (a2.z + a3.z);
    acc.w = (a0.w + a1.w) + (a2.w + a3.w);
    const float sc = 1.0f / (float)max(e - s, 1);
    acc.x *= sc; acc.y *= sc; acc.z *= sc; acc.w *= sc;
    reinterpret_cast<float4*>(AGG + (size_t)n * D)[lane] = acc;
}

// ---------------- launch -----------------------------------------------------
extern "C" void kernel_launch(void* const* d_in, const int* in_sizes, int n_in,
                              void* d_out, int out_size)
{
    const float* x     = (const float*)d_in[0];
    const void*  eidx  =               d_in[1];
    const float* Wm1   = (const float*)d_in[2];
    const float* bm1   = (const float*)d_in[3];
    const float* Wm2   = (const float*)d_in[4];
    const float* bm2   = (const float*)d_in[5];
    const float* Wu1   = (const float*)d_in[6];
    const float* bu1   = (const float*)d_in[7];
    const float* Wu2   = (const float*)d_in[8];
    const float* bu2   = (const float*)d_in[9];
    const float* gamma = (const float*)d_in[10];
    const float* beta  = (const float*)d_in[11];
    float* out = (float*)d_out;

    void *pY, *pAGG, *pROW, *pCUR, *pEIDX;
    cudaGetSymbolAddress(&pY,    g_Y);
    cudaGetSymbolAddress(&pAGG,  g_AGG);
    cudaGetSymbolAddress(&pROW,  g_ROW);
    cudaGetSymbolAddress(&pCUR,  g_CUR);
    cudaGetSymbolAddress(&pEIDX, g_EIDX);

    // smem: hdr + A hi/lo (64x136) + B hi/lo (128x136), shorts
    const int SM1 = 1024 + 2 * (64 * 136 * 2) + 2 * (128 * 136 * 2);  // 105472
    const int SM2 = 2560 + 2 * (64 * 136 * 2) + 2 * (128 * 136 * 2);  // 107008
    cudaFuncSetAttribute(msg_kernel, cudaFuncAttributeMaxDynamicSharedMemorySize, SM1);
    cudaFuncSetAttribute(upd_kernel, cudaFuncAttributeMaxDynamicSharedMemorySize, SM2);

    detect_kernel  <<<1, 32>>>((const int*)eidx);
    wsplit_kernel  <<<320, 256>>>(Wm1, Wm2, Wu1, Wu2);
    zero_cur_kernel<<<157, 256>>>((int*)pCUR);
    count_kernel   <<<2500, 256>>>(eidx, (int*)pCUR);
    scan_kernel    <<<1, 1024>>>((int*)pCUR, (int*)pROW);
    fill_kernel    <<<2500, 256>>>(eidx, (int*)pCUR, (int*)pEIDX);

    // fused message MLP (per-node, algebraically identical to per-edge)
    msg_kernel<<<625, 256, SM1>>>(x, bm1, bm2, (__half*)pY);
    // CSR gather-mean over fp16 Y
    gather_kernel<<<5000, 256>>>((const __half*)pY, (const int*)pROW,
                                 (const int*)pEIDX, (float*)pAGG);
    // fused update MLP + residual + LayerNorm
    upd_kernel<<<625, 256, SM2>>>(x, (const float*)pAGG, bu1, bu2, gamma, beta, out);
}

// round 13
// speedup vs baseline: 1.2372x; 1.1849x over previous
#include <cuda_runtime.h>
#include <cuda_bf16.h>
#include <cuda_fp16.h>
#include <cstdint>

#define N_NODES 40000
#define N_EDGES 640000
#define D 128

// ---------------- scratch (device globals: no allocations allowed) ----------
static __device__ float  g_H1 [N_NODES * D];  // msg hidden, then upd hidden (U1)
static __device__ float  g_U2 [N_NODES * D];  // pre-LN update output
static __device__ __half g_Y  [N_NODES * D];  // per-node message output (fp16)
static __device__ float  g_AGG[N_NODES * D];  // scatter-mean result
static __device__ int    g_ROW[N_NODES + 1];  // CSR row offsets (by dst)
static __device__ int    g_CUR[N_NODES];      // counts, then fill cursors
static __device__ int    g_EIDX[N_EDGES];     // src ids grouped by dst
static __device__ int    g_BSUM[64];          // block sums for scan
static __device__ int    g_is64;              // edge_index dtype flag
// pre-split weights (bf16 hi / lo), [n][k] row-major:
//   Wm1 @ 0 (16384), Wm2 @ 16384, Wu1 @ 32768 (32768), Wu2 @ 65536
static __device__ unsigned short g_Wh[81920];
static __device__ unsigned short g_Wl[81920];

// ---------------- helpers ----------------------------------------------------
__device__ __forceinline__ uint32_t smem_u32(const void* p) {
    return (uint32_t)__cvta_generic_to_shared(p);
}

// split 4 fp32 -> bf16 hi (truncate) pairs + bf16 lo (rn of residual) pairs
__device__ __forceinline__ void split4(float4 v, uint32_t& h01, uint32_t& h23,
                                       uint32_t& l01, uint32_t& l23) {
    uint32_t u0 = __float_as_uint(v.x), u1 = __float_as_uint(v.y);
    uint32_t u2 = __float_as_uint(v.z), u3 = __float_as_uint(v.w);
    asm("prmt.b32 %0, %1, %2, 0x7632;" : "=r"(h01) : "r"(u0), "r"(u1));
    asm("prmt.b32 %0, %1, %2, 0x7632;" : "=r"(h23) : "r"(u2), "r"(u3));
    float lo0 = v.x - __uint_as_float(u0 & 0xFFFF0000u);
    float lo1 = v.y - __uint_as_float(u1 & 0xFFFF0000u);
    float lo2 = v.z - __uint_as_float(u2 & 0xFFFF0000u);
    float lo3 = v.w - __uint_as_float(u3 & 0xFFFF0000u);
    asm("cvt.rn.bf16x2.f32 %0, %1, %2;" : "=r"(l01) : "f"(lo1), "f"(lo0));
    asm("cvt.rn.bf16x2.f32 %0, %1, %2;" : "=r"(l23) : "f"(lo3), "f"(lo2));
}

#define LDSM_X4(r0, r1, r2, r3, addr) \
    asm volatile("ldmatrix.sync.aligned.m8n8.x4.shared.b16 {%0,%1,%2,%3}, [%4];" \
        : "=r"(r0), "=r"(r1), "=r"(r2), "=r"(r3) : "r"(addr))

#define MMA_BF16(c, a, b) \
    asm volatile("mma.sync.aligned.m16n8k16.row.col.f32.bf16.bf16.f32 " \
        "{%0,%1,%2,%3}, {%4,%5,%6,%7}, {%8,%9}, {%0,%1,%2,%3};" \
        : "+f"((c)[0]), "+f"((c)[1]), "+f"((c)[2]), "+f"((c)[3]) \
        : "r"((a)[0]), "r"((a)[1]), "r"((a)[2]), "r"((a)[3]), \
          "r"((b)[0]), "r"((b)[1]))

// ---------------- N=64-tile GEMM: occupancy 3 CTAs/SM -----------------------
// C[:, n0:n0+64] = act(concat(A0,A1) @ W^T + bias)[:, n0:n0+64]
// Tile M=64 x N=64, K-chunk 128, 256 thr (8 warps, 2m x 4n, warp tile 32x16).
// A split to bf16 hi/lo in-kernel; W pre-split in g_Wh/g_Wl. 3-pass mma.
template <int KT, bool RELU, bool HOUT>
__global__ __launch_bounds__(256, 3)
void gemm64(const float* __restrict__ A0, const float* __restrict__ A1,
            int woff, const float* __restrict__ bias,
            float* __restrict__ Cf, __half* __restrict__ Ch)
{
    extern __shared__ char smc[];
    float* sbias = (float*)smc;                               // 64 floats
    unsigned short* sAhi = (unsigned short*)(smc + 512);      // [64][136]
    unsigned short* sAlo = sAhi + 64 * 136;
    unsigned short* sBhi = sAlo + 64 * 136;                   // [64][136]
    unsigned short* sBlo = sBhi + 64 * 136;

    const int tid  = threadIdx.x;
    const int lane = tid & 31;
    const int wid  = tid >> 5;
    const int wm   = (wid >> 2) * 32;        // 0 / 32
    const int wn   = (wid & 3) * 16;         // 0/16/32/48
    const int m0   = (blockIdx.x >> 1) * 64;
    const int n0   = (blockIdx.x & 1) * 64;

    if (tid < 64) sbias[tid] = bias[n0 + tid];

    float c[2][2][4];
    #pragma unroll
    for (int i = 0; i < 2; i++)
        #pragma unroll
        for (int j = 0; j < 2; j++)
            #pragma unroll
            for (int q = 0; q < 4; q++) c[i][j][q] = 0.0f;

    const int a_row = lane & 15, a_kh = (lane >> 4) * 8;
    const int b_row = (lane >> 4) * 8 + (lane & 7);
    const int b_kh  = ((lane >> 3) & 1) * 8;

    const int nchunks = KT / 128;
    for (int kc = 0; kc < nchunks; ++kc) {
        const float* Asrc = (kc == 0) ? A0 : A1;

        // A tile: 64x128 fp32 -> hi/lo bf16 (2048 float4, 8 iters)
        #pragma unroll
        for (int it = 0; it < 8; ++it) {
            int idx  = tid + it * 256;
            int row  = idx >> 5;
            int col4 = idx & 31;
            float4 v = *reinterpret_cast<const float4*>(
                Asrc + (size_t)(m0 + row) * D + col4 * 4);
            uint32_t h01, h23, l01, l23;
            split4(v, h01, h23, l01, l23);
            *reinterpret_cast<uint2*>(sAhi + row * 136 + col4 * 4) = make_uint2(h01, h23);
            *reinterpret_cast<uint2*>(sAlo + row * 136 + col4 * 4) = make_uint2(l01, l23);
        }
        // B tile: pre-split bf16 weights, rows n0..n0+63 (1024 uint4, 4 iters)
        #pragma unroll
        for (int it = 0; it < 4; ++it) {
            int idx = tid + it * 256;
            int row = idx >> 4;
            int c8  = idx & 15;
            size_t gsrc = (size_t)woff + (size_t)(n0 + row) * KT + kc * 128 + c8 * 8;
            *reinterpret_cast<uint4*>(sBhi + row * 136 + c8 * 8) =
                *reinterpret_cast<const uint4*>(g_Wh + gsrc);
            *reinterpret_cast<uint4*>(sBlo + row * 136 + c8 * 8) =
                *reinterpret_cast<const uint4*>(g_Wl + gsrc);
        }
        __syncthreads();

        #pragma unroll
        for (int ks = 0; ks < 8; ++ks) {
            const int kb = ks * 16;
            uint32_t ah[2][4], al[2][4], bh[2][2], bl[2][2];
            #pragma unroll
            for (int mt = 0; mt < 2; ++mt) {
                uint32_t addr = smem_u32(sAhi + (wm + mt * 16 + a_row) * 136 + kb + a_kh);
                LDSM_X4(ah[mt][0], ah[mt][1], ah[mt][2], ah[mt][3], addr);
                addr = smem_u32(sAlo + (wm + mt * 16 + a_row) * 136 + kb + a_kh);
                LDSM_X4(al[mt][0], al[mt][1], al[mt][2], al[mt][3], addr);
            }
            {
                uint32_t addr = smem_u32(sBhi + (wn + b_row) * 136 + kb + b_kh);
                LDSM_X4(bh[0][0], bh[0][1], bh[1][0], bh[1][1], addr);
                addr = smem_u32(sBlo + (wn + b_row) * 136 + kb + b_kh);
                LDSM_X4(bl[0][0], bl[0][1], bl[1][0], bl[1][1], addr);
            }
            #pragma unroll
            for (int mt = 0; mt < 2; ++mt)
                #pragma unroll
                for (int nt = 0; nt < 2; ++nt) {
                    MMA_BF16(c[mt][nt], ah[mt], bh[nt]);
                    MMA_BF16(c[mt][nt], ah[mt], bl[nt]);
                    MMA_BF16(c[mt][nt], al[mt], bh[nt]);
                }
        }
        __syncthreads();
    }

    // epilogue
    const int g = lane >> 2, cl = (lane & 3) * 2;
    #pragma unroll
    for (int mt = 0; mt < 2; ++mt) {
        const int m = m0 + wm + mt * 16 + g;
        #pragma unroll
        for (int nt = 0; nt < 2; ++nt) {
            const int nl = wn + nt * 8 + cl;
            const int n  = n0 + nl;
            float f0 = c[mt][nt][0] + sbias[nl];
            float f1 = c[mt][nt][1] + sbias[nl + 1];
            float f2 = c[mt][nt][2] + sbias[nl];
            float f3 = c[mt][nt][3] + sbias[nl + 1];
            if (RELU) {
                f0 = fmaxf(f0, 0.f); f1 = fmaxf(f1, 0.f);
                f2 = fmaxf(f2, 0.f); f3 = fmaxf(f3, 0.f);
            }
            if (HOUT) {
                *reinterpret_cast<__half2*>(Ch + (size_t)m * D + n) =
                    __float22half2_rn(make_float2(f0, f1));
                *reinterpret_cast<__half2*>(Ch + (size_t)(m + 8) * D + n) =
                    __float22half2_rn(make_float2(f2, f3));
            } else {
                *reinterpret_cast<float2*>(Cf + (size_t)m * D + n)       = make_float2(f0, f1);
                *reinterpret_cast<float2*>(Cf + (size_t)(m + 8) * D + n) = make_float2(f2, f3);
            }
        }
    }
}

// ---------------- residual + LayerNorm, one warp per row --------------------
__global__ void ln_kernel(const float* __restrict__ U, const float* __restrict__ X,
                          const float* __restrict__ gamma, const float* __restrict__ beta,
                          float* __restrict__ out)
{
    const int r    = blockIdx.x * 8 + (threadIdx.x >> 5);
    const int lane = threadIdx.x & 31;
    float4 u  = reinterpret_cast<const float4*>(U + (size_t)r * D)[lane];
    float4 xv = reinterpret_cast<const float4*>(X + (size_t)r * D)[lane];
    float4 h = make_float4(u.x + xv.x, u.y + xv.y, u.z + xv.z, u.w + xv.w);

    float s = h.x + h.y + h.z + h.w;
    #pragma unroll
    for (int o = 16; o; o >>= 1) s += __shfl_xor_sync(0xffffffffu, s, o);
    const float mu = s * (1.0f / 128.0f);

    float4 d = make_float4(h.x - mu, h.y - mu, h.z - mu, h.w - mu);
    float ss = d.x * d.x + d.y * d.y + d.z * d.z + d.w * d.w;
    #pragma unroll
    for (int o = 16; o; o >>= 1) ss += __shfl_xor_sync(0xffffffffu, ss, o);
    const float rstd = rsqrtf(ss * (1.0f / 128.0f) + 1e-5f);

    float4 gm = reinterpret_cast<const float4*>(gamma)[lane];
    float4 bt = reinterpret_cast<const float4*>(beta)[lane];
    float4 o4 = make_float4(d.x * rstd * gm.x + bt.x, d.y * rstd * gm.y + bt.y,
                            d.z * rstd * gm.z + bt.z, d.w * rstd * gm.w + bt.w);
    reinterpret_cast<float4*>(out + (size_t)r * D)[lane] = o4;
}

// ---------------- weight pre-split -------------------------------------------
__global__ void wsplit_kernel(const float* __restrict__ Wm1, const float* __restrict__ Wm2,
                              const float* __restrict__ Wu1, const float* __restrict__ Wu2)
{
    int i = blockIdx.x * blockDim.x + threadIdx.x;
    if (i >= 81920) return;
    float f;
    if      (i < 16384) f = Wm1[i];
    else if (i < 32768) f = Wm2[i - 16384];
    else if (i < 65536) f = Wu1[i - 32768];
    else                f = Wu2[i - 65536];
    uint32_t u = __float_as_uint(f);
    g_Wh[i] = (unsigned short)(u >> 16);
    float lo = f - __uint_as_float(u & 0xFFFF0000u);
    g_Wl[i] = __bfloat16_as_ushort(__float2bfloat16(lo));
}

// ---------------- edge dtype sniff -------------------------------------------
__global__ void detect_kernel(const int* __restrict__ e) {
    if (threadIdx.x == 0) {
        int any = 0;
        for (int i = 1; i < 256; i += 2) any |= e[i];
        g_is64 = (any == 0) ? 1 : 0;
    }
}

// ---------------- CSR build (scatter-mean without float atomics) ------------
__global__ void zero_cur_kernel(int* __restrict__ CUR) {
    int i = blockIdx.x * blockDim.x + threadIdx.x;
    if (i < N_NODES) CUR[i] = 0;
}
__global__ void count_kernel(const void* __restrict__ eidx, int* __restrict__ CUR) {
    int e = blockIdx.x * blockDim.x + threadIdx.x;     // 2500*256 = E exact
    int dst = g_is64 ? (int)reinterpret_cast<const long long*>(eidx)[N_EDGES + e]
                     : reinterpret_cast<const int*>(eidx)[N_EDGES + e];
    atomicAdd(&CUR[dst], 1);
}
// hierarchical scan: per-block inclusive scan -> local exclusive ROW + BSUM
__global__ void scanA_kernel(const int* __restrict__ CUR, int* __restrict__ ROW,
                             int* __restrict__ BSUM) {
    __shared__ int s[1024];
    const int t = threadIdx.x;
    const int i = blockIdx.x * 1024 + t;
    int v = (i < N_NODES) ? CUR[i] : 0;
    s[t] = v;
    __syncthreads();
    for (int off = 1; off < 1024; off <<= 1) {
        int tmp = (t >= off) ? s[t - off] : 0;
        __syncthreads();
        s[t] += tmp;
        __syncthreads();
    }
    if (i < N_NODES) ROW[i] = s[t] - v;   // local exclusive
    if (t == 1023) BSUM[blockIdx.x] = s[1023];
}
__global__ void scanB_kernel(int* __restrict__ BSUM, int* __restrict__ ROW) {
    if (threadIdx.x == 0) {
        int run = 0;
        for (int b = 0; b < 40; b++) { int cv = BSUM[b]; BSUM[b] = run; run += cv; }
        ROW[N_NODES] = N_EDGES;
    }
}
__global__ void scanC_kernel(int* __restrict__ ROW, const int* __restrict__ BSUM,
                             int* __restrict__ CUR) {
    const int i = blockIdx.x * 1024 + threadIdx.x;
    if (i < N_NODES) {
        int r = ROW[i] + BSUM[blockIdx.x];
        ROW[i] = r;
        CUR[i] = r;       // cursor for fill
    }
}
__global__ void fill_kernel(const void* __restrict__ eidx, int* __restrict__ CUR,
                            int* __restrict__ EIDX) {
    int e = blockIdx.x * blockDim.x + threadIdx.x;
    int src, dst;
    if (g_is64) {
        const long long* p = reinterpret_cast<const long long*>(eidx);
        src = (int)p[e]; dst = (int)p[N_EDGES + e];
    } else {
        const int* p = reinterpret_cast<const int*>(eidx);
        src = p[e]; dst = p[N_EDGES + e];
    }
    int pos = atomicAdd(&CUR[dst], 1);
    EIDX[pos] = src;
}
// one warp per node: sum fp16 Y[src] over incoming edges, divide by degree.
__global__ void gather_kernel(const __half* __restrict__ Y, const int* __restrict__ ROW,
                              const int* __restrict__ EIDX, float* __restrict__ AGG) {
    const int n    = blockIdx.x * 8 + (threadIdx.x >> 5);
    const int lane = threadIdx.x & 31;
    const int s = ROW[n], e = ROW[n + 1];
    float4 a0 = make_float4(0.f, 0.f, 0.f, 0.f);
    float4 a1 = make_float4(0.f, 0.f, 0.f, 0.f);
    float4 a2 = make_float4(0.f, 0.f, 0.f, 0.f);
    float4 a3 = make_float4(0.f, 0.f, 0.f, 0.f);
    for (int base = s; base < e; base += 32) {
        const int cnt = min(32, e - base);
        int idx = (base + lane < e) ? EIDX[base + lane] : 0;
        int j = 0;
        for (; j + 4 <= cnt; j += 4) {
            int s0 = __shfl_sync(0xffffffffu, idx, j);
            int s1 = __shfl_sync(0xffffffffu, idx, j + 1);
            int s2 = __shfl_sync(0xffffffffu, idx, j + 2);
            int s3 = __shfl_sync(0xffffffffu, idx, j + 3);
            uint2 r0 = *reinterpret_cast<const uint2*>(Y + (size_t)s0 * D + lane * 4);
            uint2 r1 = *reinterpret_cast<const uint2*>(Y + (size_t)s1 * D + lane * 4);
            uint2 r2 = *reinterpret_cast<const uint2*>(Y + (size_t)s2 * D + lane * 4);
            uint2 r3 = *reinterpret_cast<const uint2*>(Y + (size_t)s3 * D + lane * 4);
            float2 f;
            f = __half22float2(*(__half2*)&r0.x); a0.x += f.x; a0.y += f.y;
            f = __half22float2(*(__half2*)&r0.y); a0.z += f.x; a0.w += f.y;
            f = __half22float2(*(__half2*)&r1.x); a1.x += f.x; a1.y += f.y;
            f = __half22float2(*(__half2*)&r1.y); a1.z += f.x; a1.w += f.y;
            f = __half22float2(*(__half2*)&r2.x); a2.x += f.x; a2.y += f.y;
            f = __half22float2(*(__half2*)&r2.y); a2.z += f.x; a2.w += f.y;
            f = __half22float2(*(__half2*)&r3.x); a3.x += f.x; a3.y += f.y;
            f = __half22float2(*(__half2*)&r3.y); a3.z += f.x; a3.w += f.y;
        }
        for (; j < cnt; ++j) {
            int s0 = __shfl_sync(0xffffffffu, idx, j);
            uint2 r0 = *reinterpret_cast<const uint2*>(Y + (size_t)s0 * D + lane * 4);
            float2 f;
            f = __half22float2(*(__half2*)&r0.x); a0.x += f.x; a0.y += f.y;
            f = __half22float2(*(__half2*)&r0.y); a0.z += f.x; a0.w += f.y;
        }
    }
    float4 acc;
    acc.x = (a0.x + a1.x) + (a2.x + a3.x);
    acc.y = (a0.y + a1.y) + (a2.y + a3.y);
    acc.z = (a0.z + a1.z) + (a2.z + a3.z);
    acc.w = (a0.w + a1.w) + (a2.w + a3.w);
    const float sc = 1.0f / (float)max(e - s, 1);
    acc.x *= sc; acc.y *= sc; acc.z *= sc; acc.w *= sc;
    reinterpret_cast<float4*>(AGG + (size_t)n * D)[lane] = acc;
}

// ---------------- launch -----------------------------------------------------
extern "C" void kernel_launch(void* const* d_in, const int* in_sizes, int n_in,
                              void* d_out, int out_size)
{
    const float* x     = (const float*)d_in[0];
    const void*  eidx  =               d_in[1];
    const float* Wm1   = (const float*)d_in[2];
    const float* bm1   = (const float*)d_in[3];
    const float* Wm2   = (const float*)d_in[4];
    const float* bm2   = (const float*)d_in[5];
    const float* Wu1   = (const float*)d_in[6];
    const float* bu1   = (const float*)d_in[7];
    const float* Wu2   = (const float*)d_in[8];
    const float* bu2   = (const float*)d_in[9];
    const float* gamma = (const float*)d_in[10];
    const float* beta  = (const float*)d_in[11];
    float* out = (float*)d_out;

    void *pH1, *pU2, *pY, *pAGG, *pROW, *pCUR, *pEIDX, *pBSUM;
    cudaGetSymbolAddress(&pH1,   g_H1);
    cudaGetSymbolAddress(&pU2,   g_U2);
    cudaGetSymbolAddress(&pY,    g_Y);
    cudaGetSymbolAddress(&pAGG,  g_AGG);
    cudaGetSymbolAddress(&pROW,  g_ROW);
    cudaGetSymbolAddress(&pCUR,  g_CUR);
    cudaGetSymbolAddress(&pEIDX, g_EIDX);
    cudaGetSymbolAddress(&pBSUM, g_BSUM);

    // smem: 512 hdr + A hi/lo + B hi/lo, each 64x136 shorts
    const int SM64 = 512 + 4 * (64 * 136 * 2);   // 70144 -> 3 CTAs/SM
    cudaFuncSetAttribute(gemm64<128, true,  false>, cudaFuncAttributeMaxDynamicSharedMemorySize, SM64);
    cudaFuncSetAttribute(gemm64<128, false, true >, cudaFuncAttributeMaxDynamicSharedMemorySize, SM64);
    cudaFuncSetAttribute(gemm64<256, true,  false>, cudaFuncAttributeMaxDynamicSharedMemorySize, SM64);
    cudaFuncSetAttribute(gemm64<128, false, false>, cudaFuncAttributeMaxDynamicSharedMemorySize, SM64);

    const int GG = 1250;   // 625 m-tiles x 2 n-tiles

    detect_kernel  <<<1, 32>>>((const int*)eidx);
    wsplit_kernel  <<<320, 256>>>(Wm1, Wm2, Wu1, Wu2);
    zero_cur_kernel<<<157, 256>>>((int*)pCUR);
    count_kernel   <<<2500, 256>>>(eidx, (int*)pCUR);
    scanA_kernel   <<<40, 1024>>>((const int*)pCUR, (int*)pROW, (int*)pBSUM);
    scanB_kernel   <<<1, 32>>>((int*)pBSUM, (int*)pROW);
    scanC_kernel   <<<40, 1024>>>((int*)pROW, (const int*)pBSUM, (int*)pCUR);
    fill_kernel    <<<2500, 256>>>(eidx, (int*)pCUR, (int*)pEIDX);

    // message MLP (per-node, algebraically identical to per-edge)
    gemm64<128, true,  false><<<GG, 256, SM64>>>(x, nullptr, 0,     bm1, (float*)pH1, nullptr);
    gemm64<128, false, true ><<<GG, 256, SM64>>>((const float*)pH1, nullptr, 16384, bm2, nullptr, (__half*)pY);
    // CSR gather-mean over fp16 Y
    gather_kernel<<<5000, 256>>>((const __half*)pY, (const int*)pROW,
                                 (const int*)pEIDX, (float*)pAGG);
    // update MLP on concat([x, agg])
    gemm64<256, true,  false><<<GG, 256, SM64>>>(x, (const float*)pAGG, 32768, bu1, (float*)pH1, nullptr);
    gemm64<128, false, false><<<GG, 256, SM64>>>((const float*)pH1, nullptr, 65536, bu2, (float*)pU2, nullptr);
    // residual + LayerNorm
    ln_kernel<<<5000, 256>>>((const float*)pU2, x, gamma, beta, out);
}